// round 9
// baseline (speedup 1.0000x reference)
#include <cuda_runtime.h>
#include <cuda_fp16.h>
#include <cstdint>

// ---------------------------------------------------------------------------
// Problem constants
// ---------------------------------------------------------------------------
#define IN_F   4096
#define OUT_F  4096
#define BLOCK_ 16
#define D_LAT  16
#define HID    64
#define KSIZE  65536
#define NB     (IN_F * OUT_F / BLOCK_)
#define M_ROWS 8192
#define K_DIM  4096
#define N_DIM  4096

// GEMM tiling: CTA 256x128, 8 warps of 64x64 (4x2), BK=64, 4 stages
#define BM 256
#define BN 128
#define BK 64
#define STAGES 4
#define NK (K_DIM / BK)   // 64
#define THREADS 256

// ---------------------------------------------------------------------------
// Scratch
// ---------------------------------------------------------------------------
__device__ float  g_table[(size_t)KSIZE * BLOCK_];
__device__ __half g_Wh[(size_t)OUT_F * IN_F];
__device__ __half g_xh[(size_t)M_ROWS * IN_F];

// ---------------------------------------------------------------------------
// Helpers
// ---------------------------------------------------------------------------
__device__ __forceinline__ uint32_t smem_u32(const void* p) {
    return (uint32_t)__cvta_generic_to_shared(p);
}
#define SWZ(o) ((o) ^ (((o) >> 3) & 0x70))

__device__ __forceinline__ void cp16(uint32_t saddr, const void* gaddr) {
    asm volatile("cp.async.cg.shared.global [%0], [%1], 16;" :: "r"(saddr), "l"(gaddr));
}
#define CP_COMMIT() asm volatile("cp.async.commit_group;" ::: "memory")
#define CP_WAIT2()  asm volatile("cp.async.wait_group 2;" ::: "memory")

__device__ __forceinline__ void ldm_x4(uint32_t addr, uint32_t& r0, uint32_t& r1,
                                       uint32_t& r2, uint32_t& r3) {
    asm volatile("ldmatrix.sync.aligned.m8n8.x4.shared.b16 {%0,%1,%2,%3}, [%4];"
                 : "=r"(r0), "=r"(r1), "=r"(r2), "=r"(r3) : "r"(addr));
}

__device__ __forceinline__ void mma16816(float& c0, float& c1, float& c2, float& c3,
                                         uint32_t a0, uint32_t a1, uint32_t a2, uint32_t a3,
                                         uint32_t b0, uint32_t b1) {
    asm volatile("mma.sync.aligned.m16n8k16.row.col.f32.f16.f16.f32 "
                 "{%0,%1,%2,%3}, {%4,%5,%6,%7}, {%8,%9}, {%0,%1,%2,%3};"
                 : "+f"(c0), "+f"(c1), "+f"(c2), "+f"(c3)
                 : "r"(a0), "r"(a1), "r"(a2), "r"(a3), "r"(b0), "r"(b1));
}

// ---------------------------------------------------------------------------
// Kernel 1: decode every codebook entry once (65536 x 16), float4 LDS.
// ---------------------------------------------------------------------------
__global__ void __launch_bounds__(256)
precompute_table(const float* __restrict__ codebook,
                 const float* __restrict__ W1, const float* __restrict__ b1,
                 const float* __restrict__ W2, const float* __restrict__ b2)
{
    __shared__ __align__(16) float sW1[D_LAT * HID];
    __shared__ __align__(16) float sW2[HID * BLOCK_];
    __shared__ __align__(16) float sb1[HID];
    __shared__ __align__(16) float sb2[BLOCK_];

    const int tid = threadIdx.x;
    for (int i = tid; i < D_LAT * HID; i += 256) sW1[i] = W1[i];
    for (int i = tid; i < HID * BLOCK_; i += 256) sW2[i] = W2[i];
    if (tid < HID)    sb1[tid] = b1[tid];
    if (tid < BLOCK_) sb2[tid] = b2[tid];
    __syncthreads();

    const int e = blockIdx.x * 256 + tid;

    float c[D_LAT];
    const float4* cb = reinterpret_cast<const float4*>(codebook + (size_t)e * D_LAT);
    {
        float4 v0 = cb[0], v1 = cb[1], v2 = cb[2], v3 = cb[3];
        c[0]=v0.x; c[1]=v0.y; c[2]=v0.z; c[3]=v0.w;
        c[4]=v1.x; c[5]=v1.y; c[6]=v1.z; c[7]=v1.w;
        c[8]=v2.x; c[9]=v2.y; c[10]=v2.z; c[11]=v2.w;
        c[12]=v3.x; c[13]=v3.y; c[14]=v3.z; c[15]=v3.w;
    }

    float h[HID];
    #pragma unroll
    for (int j4 = 0; j4 < HID; j4 += 4) {
        float4 b4 = *reinterpret_cast<const float4*>(&sb1[j4]);
        h[j4+0] = b4.x; h[j4+1] = b4.y; h[j4+2] = b4.z; h[j4+3] = b4.w;
    }
    #pragma unroll
    for (int d = 0; d < D_LAT; ++d) {
        const float cd = c[d];
        #pragma unroll
        for (int j4 = 0; j4 < HID; j4 += 4) {
            float4 w4 = *reinterpret_cast<const float4*>(&sW1[d * HID + j4]);
            h[j4+0] = fmaf(cd, w4.x, h[j4+0]);
            h[j4+1] = fmaf(cd, w4.y, h[j4+1]);
            h[j4+2] = fmaf(cd, w4.z, h[j4+2]);
            h[j4+3] = fmaf(cd, w4.w, h[j4+3]);
        }
    }
    #pragma unroll
    for (int j = 0; j < HID; ++j) h[j] = fmaxf(h[j], 0.0f);

    float blk[BLOCK_];
    #pragma unroll
    for (int k4 = 0; k4 < BLOCK_; k4 += 4) {
        float4 b4 = *reinterpret_cast<const float4*>(&sb2[k4]);
        blk[k4+0] = b4.x; blk[k4+1] = b4.y; blk[k4+2] = b4.z; blk[k4+3] = b4.w;
    }
    #pragma unroll
    for (int j = 0; j < HID; ++j) {
        const float hj = h[j];
        #pragma unroll
        for (int k4 = 0; k4 < BLOCK_; k4 += 4) {
            float4 w4 = *reinterpret_cast<const float4*>(&sW2[j * BLOCK_ + k4]);
            blk[k4+0] = fmaf(hj, w4.x, blk[k4+0]);
            blk[k4+1] = fmaf(hj, w4.y, blk[k4+1]);
            blk[k4+2] = fmaf(hj, w4.z, blk[k4+2]);
            blk[k4+3] = fmaf(hj, w4.w, blk[k4+3]);
        }
    }

    float4* dst = reinterpret_cast<float4*>(g_table + (size_t)e * BLOCK_);
    dst[0] = make_float4(blk[0], blk[1], blk[2], blk[3]);
    dst[1] = make_float4(blk[4], blk[5], blk[6], blk[7]);
    dst[2] = make_float4(blk[8], blk[9], blk[10], blk[11]);
    dst[3] = make_float4(blk[12], blk[13], blk[14], blk[15]);
}

// ---------------------------------------------------------------------------
// Kernel 2 (fused): gather+destandardize W  AND  convert x -> fp16.
// ---------------------------------------------------------------------------
#define XCONV_BLOCKS ((M_ROWS * K_DIM) / (256 * 8))   // 16384

__global__ void __launch_bounds__(256)
prep_kernel(const int* __restrict__ idx,
            const float* __restrict__ scale, const float* __restrict__ shift,
            const float* __restrict__ x)
{
    if (blockIdx.x < OUT_F) {
        __shared__ float s_s, s_sh;
        const int o = blockIdx.x;
        if (threadIdx.x == 0) { s_s = scale[o]; s_sh = shift[o]; }
        __syncthreads();

        const int b = o * 256 + threadIdx.x;
        const int e = idx[b];
        const float s  = s_s;
        const float sh = s_sh;

        const float4* src = reinterpret_cast<const float4*>(g_table + (size_t)e * BLOCK_);
        float4 v0 = src[0], v1 = src[1], v2 = src[2], v3 = src[3];
        float blk[16] = {v0.x,v0.y,v0.z,v0.w, v1.x,v1.y,v1.z,v1.w,
                         v2.x,v2.y,v2.z,v2.w, v3.x,v3.y,v3.z,v3.w};

        __align__(16) __half h16[16];
        #pragma unroll
        for (int q = 0; q < 16; ++q) h16[q] = __float2half_rn(fmaf(blk[q], s, sh));

        const size_t base = (size_t)o * IN_F + (size_t)threadIdx.x * 16;
        reinterpret_cast<uint4*>(g_Wh + base)[0] = reinterpret_cast<uint4*>(h16)[0];
        reinterpret_cast<uint4*>(g_Wh + base)[1] = reinterpret_cast<uint4*>(h16)[1];
    } else {
        const size_t t = (size_t)(blockIdx.x - OUT_F) * 256 + threadIdx.x;
        const size_t base = t * 8;
        float4 a = *reinterpret_cast<const float4*>(x + base);
        float4 b = *reinterpret_cast<const float4*>(x + base + 4);
        __align__(16) __half h[8];
        h[0]=__float2half_rn(a.x); h[1]=__float2half_rn(a.y);
        h[2]=__float2half_rn(a.z); h[3]=__float2half_rn(a.w);
        h[4]=__float2half_rn(b.x); h[5]=__float2half_rn(b.y);
        h[6]=__float2half_rn(b.z); h[7]=__float2half_rn(b.w);
        *reinterpret_cast<uint4*>(g_xh + base) = *reinterpret_cast<uint4*>(h);
    }
}

// ---------------------------------------------------------------------------
// Kernel 3: fp16 mma.sync GEMM. CTA 256x128, 8 warps 64x64, 4-stage pipeline.
// 4 buffers give: 2-iteration cp.async landing window AND guaranteed
// next-stage residency at kk=3 (wait_group 2 retires stage it+1, issued 2
// iterations earlier) -> cross-iteration kk0 fragment preload with no bubble.
// ---------------------------------------------------------------------------
#define A_BYTES (BM * 128)                 // 32768
#define B_BYTES (BN * 128)                 // 16384
#define STG_BYTES (A_BYTES + B_BYTES)      // 49152
#define SMEM_TOTAL (STAGES * STG_BYTES)    // 196608 (192 KB), 1 CTA/SM

__device__ __forceinline__ void load_stage(uint32_t sbase, int buf, int it,
                                           int bm0, int bn0, int tid)
{
    const uint32_t sA = sbase + buf * STG_BYTES;
    const uint32_t sB = sA + A_BYTES;
    const size_t k0 = (size_t)it * BK;
    #pragma unroll
    for (int i = 0; i < 8; ++i) {                 // A: 256 rows x 8 chunks
        const int c = tid + i * 256;
        const int row = c >> 3;
        const int cx  = c & 7;
        const uint32_t soff = SWZ((uint32_t)(row * 128 + cx * 16));
        cp16(sA + soff, g_xh + (size_t)(bm0 + row) * K_DIM + k0 + cx * 8);
    }
    #pragma unroll
    for (int i = 0; i < 4; ++i) {                 // B: 128 rows x 8 chunks
        const int c = tid + i * 256;
        const int row = c >> 3;
        const int cx  = c & 7;
        const uint32_t soff = SWZ((uint32_t)(row * 128 + cx * 16));
        cp16(sB + soff, g_Wh + (size_t)(bn0 + row) * K_DIM + k0 + cx * 8);
    }
}

__global__ void __launch_bounds__(THREADS, 1)
gemm_kernel(const float* __restrict__ bias, float* __restrict__ C)
{
    extern __shared__ char smem[];
    const uint32_t sbase = smem_u32(smem);
    const int tid  = threadIdx.x;
    const int lane = tid & 31;
    const int w    = tid >> 5;          // 0..7
    const int wm   = w >> 1;            // 0..3 -> m offset wm*64
    const int wn   = w & 1;             // 0..1 -> n offset wn*64
    const int bm0  = blockIdx.y * BM;
    const int bn0  = blockIdx.x * BN;

    float acc[4][8][4];
    #pragma unroll
    for (int mt = 0; mt < 4; ++mt)
        #pragma unroll
        for (int nt = 0; nt < 8; ++nt)
            #pragma unroll
            for (int q = 0; q < 4; ++q) acc[mt][nt][q] = 0.0f;

    // Prologue: fill buffers 0,1,2
    load_stage(sbase, 0, 0, bm0, bn0, tid);
    CP_COMMIT();
    load_stage(sbase, 1, 1, bm0, bn0, tid);
    CP_COMMIT();
    load_stage(sbase, 2, 2, bm0, bn0, tid);
    CP_COMMIT();

    // Per-lane ldmatrix base offsets
    const int a_row = wm * 64 + (lane & 15);
    const int a_cb  = ((lane >> 4) & 1) * 16;
    const int b_row = wn * 64 + ((lane >> 4) & 1) * 8 + (lane & 7);
    const int b_cb  = ((lane >> 3) & 1) * 16;

    uint32_t a[2][4][4];
    uint32_t b[2][8][2];

    // Wait for stage 0 (<=2 outstanding), preload its kk=0 fragments.
    CP_WAIT2();
    __syncthreads();
    {
        const uint32_t sA = sbase;
        const uint32_t sB = sA + A_BYTES;
        #pragma unroll
        for (int mt = 0; mt < 4; ++mt) {
            const uint32_t off = (uint32_t)((a_row + mt * 16) * 128 + a_cb);
            ldm_x4(sA + SWZ(off), a[0][mt][0], a[0][mt][1], a[0][mt][2], a[0][mt][3]);
        }
        #pragma unroll
        for (int ntp = 0; ntp < 4; ++ntp) {
            const uint32_t off = (uint32_t)((b_row + ntp * 16) * 128 + b_cb);
            uint32_t r0, r1, r2, r3;
            ldm_x4(sB + SWZ(off), r0, r1, r2, r3);
            b[0][ntp*2+0][0] = r0; b[0][ntp*2+0][1] = r1;
            b[0][ntp*2+1][0] = r2; b[0][ntp*2+1][1] = r3;
        }
    }

    for (int it = 0; it < NK; ++it) {
        // Buffer (it+3)%4 was fully consumed in iteration it-1.
        __syncthreads();

        const int nxt = it + 3;
        if (nxt < NK) load_stage(sbase, nxt % STAGES, nxt, bm0, bn0, tid);
        CP_COMMIT();   // outstanding: {it+1, it+2, it+3}

        const uint32_t sA = sbase + (it % STAGES) * STG_BYTES;
        const uint32_t sB = sA + A_BYTES;
        const uint32_t sAn = sbase + ((it + 1) % STAGES) * STG_BYTES;
        const uint32_t sBn = sAn + A_BYTES;
        const bool have_next = (it + 1) < NK;

        // kk = 0..2: prefetch kk+1 frags from current stage, MMA kk
        #pragma unroll
        for (int kk = 0; kk < 3; ++kk) {
            const int cur = kk & 1;
            const int nxb = cur ^ 1;
            const int kc = (kk + 1) * 32;
            #pragma unroll
            for (int mt = 0; mt < 4; ++mt) {
                const uint32_t off = (uint32_t)((a_row + mt * 16) * 128 + kc + a_cb);
                ldm_x4(sA + SWZ(off), a[nxb][mt][0], a[nxb][mt][1], a[nxb][mt][2], a[nxb][mt][3]);
            }
            #pragma unroll
            for (int ntp = 0; ntp < 4; ++ntp) {
                const uint32_t off = (uint32_t)((b_row + ntp * 16) * 128 + kc + b_cb);
                uint32_t r0, r1, r2, r3;
                ldm_x4(sB + SWZ(off), r0, r1, r2, r3);
                b[nxb][ntp*2+0][0] = r0; b[nxb][ntp*2+0][1] = r1;
                b[nxb][ntp*2+1][0] = r2; b[nxb][ntp*2+1][1] = r3;
            }
            #pragma unroll
            for (int mt = 0; mt < 4; ++mt)
                #pragma unroll
                for (int nt = 0; nt < 8; ++nt)
                    mma16816(acc[mt][nt][0], acc[mt][nt][1], acc[mt][nt][2], acc[mt][nt][3],
                             a[cur][mt][0], a[cur][mt][1], a[cur][mt][2], a[cur][mt][3],
                             b[cur][nt][0], b[cur][nt][1]);
        }

        // Retire stage it+1 (issued 2 iterations ago; ample landing time).
        CP_WAIT2();

        // kk = 3: preload NEXT stage's kk=0 frags (buffer parity 0), MMA kk=3
        {
            if (have_next) {
                #pragma unroll
                for (int mt = 0; mt < 4; ++mt) {
                    const uint32_t off = (uint32_t)((a_row + mt * 16) * 128 + a_cb);
                    ldm_x4(sAn + SWZ(off), a[0][mt][0], a[0][mt][1], a[0][mt][2], a[0][mt][3]);
                }
                #pragma unroll
                for (int ntp = 0; ntp < 4; ++ntp) {
                    const uint32_t off = (uint32_t)((b_row + ntp * 16) * 128 + b_cb);
                    uint32_t r0, r1, r2, r3;
                    ldm_x4(sBn + SWZ(off), r0, r1, r2, r3);
                    b[0][ntp*2+0][0] = r0; b[0][ntp*2+0][1] = r1;
                    b[0][ntp*2+1][0] = r2; b[0][ntp*2+1][1] = r3;
                }
            }
            #pragma unroll
            for (int mt = 0; mt < 4; ++mt)
                #pragma unroll
                for (int nt = 0; nt < 8; ++nt)
                    mma16816(acc[mt][nt][0], acc[mt][nt][1], acc[mt][nt][2], acc[mt][nt][3],
                             a[1][mt][0], a[1][mt][1], a[1][mt][2], a[1][mt][3],
                             b[1][nt][0], b[1][nt][1]);
        }
    }

    // Epilogue
    #pragma unroll
    for (int nt = 0; nt < 8; ++nt) {
        const int col = bn0 + wn * 64 + nt * 8 + (lane & 3) * 2;
        const float bx = __ldg(bias + col);
        const float by = __ldg(bias + col + 1);
        #pragma unroll
        for (int mt = 0; mt < 4; ++mt) {
            const int r0 = bm0 + wm * 64 + mt * 16 + (lane >> 2);
            float2 v0 = make_float2(acc[mt][nt][0] + bx, acc[mt][nt][1] + by);
            float2 v1 = make_float2(acc[mt][nt][2] + bx, acc[mt][nt][3] + by);
            *reinterpret_cast<float2*>(C + (size_t)r0 * N_DIM + col) = v0;
            *reinterpret_cast<float2*>(C + (size_t)(r0 + 8) * N_DIM + col) = v1;
        }
    }
}

// ---------------------------------------------------------------------------
// kernel_launch
// ---------------------------------------------------------------------------
extern "C" void kernel_launch(void* const* d_in, const int* in_sizes, int n_in,
                              void* d_out, int out_size)
{
    const float* x        = (const float*)d_in[0];
    const int*   y_in_idx = (const int*)  d_in[1];
    const float* codebook = (const float*)d_in[2];
    const float* W1       = (const float*)d_in[3];
    const float* b1       = (const float*)d_in[4];
    const float* W2       = (const float*)d_in[5];
    const float* b2       = (const float*)d_in[6];
    const float* scale    = (const float*)d_in[7];
    const float* shift    = (const float*)d_in[8];
    const float* bias     = (const float*)d_in[9];
    float* out = (float*)d_out;

    cudaFuncSetAttribute(gemm_kernel, cudaFuncAttributeMaxDynamicSharedMemorySize, SMEM_TOTAL);

    precompute_table<<<KSIZE / 256, 256>>>(codebook, W1, b1, W2, b2);
    prep_kernel<<<OUT_F + XCONV_BLOCKS, 256>>>(y_in_idx, scale, shift, x);

    dim3 grid(N_DIM / BN, M_ROWS / BM);
    gemm_kernel<<<grid, THREADS, SMEM_TOTAL>>>(bias, out);
}

// round 10
// speedup vs baseline: 1.4669x; 1.4669x over previous
#include <cuda_runtime.h>
#include <cuda_fp16.h>
#include <cstdint>

// ---------------------------------------------------------------------------
// Problem constants
// ---------------------------------------------------------------------------
#define IN_F   4096
#define OUT_F  4096
#define BLOCK_ 16
#define D_LAT  16
#define HID    64
#define KSIZE  65536
#define NB     (IN_F * OUT_F / BLOCK_)
#define M_ROWS 8192
#define K_DIM  4096
#define N_DIM  4096

// GEMM tiling: CTA 128x128, 4 warps of 64x64, BK=64, 3 stages (R5 config)
#define BM 128
#define BN 128
#define BK 64
#define STAGES 3
#define NK (K_DIM / BK)   // 64
#define THREADS 128

// ---------------------------------------------------------------------------
// Scratch
// ---------------------------------------------------------------------------
__device__ float  g_table[(size_t)KSIZE * BLOCK_];
__device__ __half g_Wh[(size_t)OUT_F * IN_F];
__device__ __half g_xh[(size_t)M_ROWS * IN_F];

// ---------------------------------------------------------------------------
// Helpers
// ---------------------------------------------------------------------------
__device__ __forceinline__ uint32_t smem_u32(const void* p) {
    return (uint32_t)__cvta_generic_to_shared(p);
}
#define SWZ(o) ((o) ^ (((o) >> 3) & 0x70))

__device__ __forceinline__ void cp16(uint32_t saddr, const void* gaddr) {
    asm volatile("cp.async.cg.shared.global [%0], [%1], 16;" :: "r"(saddr), "l"(gaddr));
}
#define CP_COMMIT() asm volatile("cp.async.commit_group;" ::: "memory")
#define CP_WAIT1()  asm volatile("cp.async.wait_group 1;" ::: "memory")

__device__ __forceinline__ void ldm_x4(uint32_t addr, uint32_t& r0, uint32_t& r1,
                                       uint32_t& r2, uint32_t& r3) {
    asm volatile("ldmatrix.sync.aligned.m8n8.x4.shared.b16 {%0,%1,%2,%3}, [%4];"
                 : "=r"(r0), "=r"(r1), "=r"(r2), "=r"(r3) : "r"(addr));
}

__device__ __forceinline__ void mma16816(float& c0, float& c1, float& c2, float& c3,
                                         uint32_t a0, uint32_t a1, uint32_t a2, uint32_t a3,
                                         uint32_t b0, uint32_t b1) {
    asm volatile("mma.sync.aligned.m16n8k16.row.col.f32.f16.f16.f32 "
                 "{%0,%1,%2,%3}, {%4,%5,%6,%7}, {%8,%9}, {%0,%1,%2,%3};"
                 : "+f"(c0), "+f"(c1), "+f"(c2), "+f"(c3)
                 : "r"(a0), "r"(a1), "r"(a2), "r"(a3), "r"(b0), "r"(b1));
}

// ---------------------------------------------------------------------------
// Kernel 1 (fused, independent halves running concurrently):
//   blocks [0, TBL_BLOCKS): decode codebook entries (scalar LDS — R7 best)
//   blocks [TBL_BLOCKS, +XCONV_BLOCKS): convert x -> fp16
// ---------------------------------------------------------------------------
#define TBL_BLOCKS   (KSIZE / 256)                    // 256
#define XCONV_BLOCKS ((M_ROWS * K_DIM) / (256 * 8))   // 16384

__global__ void __launch_bounds__(256)
table_and_x_kernel(const float* __restrict__ codebook,
                   const float* __restrict__ W1, const float* __restrict__ b1,
                   const float* __restrict__ W2, const float* __restrict__ b2,
                   const float* __restrict__ x)
{
    if (blockIdx.x < TBL_BLOCKS) {
        __shared__ float sW1[D_LAT * HID];
        __shared__ float sW2[HID * BLOCK_];
        __shared__ float sb1[HID];
        __shared__ float sb2[BLOCK_];

        const int tid = threadIdx.x;
        for (int i = tid; i < D_LAT * HID; i += 256) sW1[i] = W1[i];
        for (int i = tid; i < HID * BLOCK_; i += 256) sW2[i] = W2[i];
        if (tid < HID)    sb1[tid] = b1[tid];
        if (tid < BLOCK_) sb2[tid] = b2[tid];
        __syncthreads();

        const int e = blockIdx.x * 256 + tid;

        float c[D_LAT];
        const float4* cb = reinterpret_cast<const float4*>(codebook + (size_t)e * D_LAT);
        {
            float4 v0 = cb[0], v1 = cb[1], v2 = cb[2], v3 = cb[3];
            c[0]=v0.x; c[1]=v0.y; c[2]=v0.z; c[3]=v0.w;
            c[4]=v1.x; c[5]=v1.y; c[6]=v1.z; c[7]=v1.w;
            c[8]=v2.x; c[9]=v2.y; c[10]=v2.z; c[11]=v2.w;
            c[12]=v3.x; c[13]=v3.y; c[14]=v3.z; c[15]=v3.w;
        }

        float h[HID];
        #pragma unroll
        for (int j = 0; j < HID; ++j) h[j] = sb1[j];
        #pragma unroll
        for (int d = 0; d < D_LAT; ++d) {
            const float cd = c[d];
            #pragma unroll
            for (int j = 0; j < HID; ++j) h[j] = fmaf(cd, sW1[d * HID + j], h[j]);
        }
        #pragma unroll
        for (int j = 0; j < HID; ++j) h[j] = fmaxf(h[j], 0.0f);

        float blk[BLOCK_];
        #pragma unroll
        for (int k = 0; k < BLOCK_; ++k) blk[k] = sb2[k];
        #pragma unroll
        for (int j = 0; j < HID; ++j) {
            const float hj = h[j];
            #pragma unroll
            for (int k = 0; k < BLOCK_; ++k) blk[k] = fmaf(hj, sW2[j * BLOCK_ + k], blk[k]);
        }

        float4* dst = reinterpret_cast<float4*>(g_table + (size_t)e * BLOCK_);
        dst[0] = make_float4(blk[0], blk[1], blk[2], blk[3]);
        dst[1] = make_float4(blk[4], blk[5], blk[6], blk[7]);
        dst[2] = make_float4(blk[8], blk[9], blk[10], blk[11]);
        dst[3] = make_float4(blk[12], blk[13], blk[14], blk[15]);
    } else {
        const size_t t = (size_t)(blockIdx.x - TBL_BLOCKS) * 256 + threadIdx.x;
        const size_t base = t * 8;
        float4 a = *reinterpret_cast<const float4*>(x + base);
        float4 b = *reinterpret_cast<const float4*>(x + base + 4);
        __align__(16) __half h[8];
        h[0]=__float2half_rn(a.x); h[1]=__float2half_rn(a.y);
        h[2]=__float2half_rn(a.z); h[3]=__float2half_rn(a.w);
        h[4]=__float2half_rn(b.x); h[5]=__float2half_rn(b.y);
        h[6]=__float2half_rn(b.z); h[7]=__float2half_rn(b.w);
        *reinterpret_cast<uint4*>(g_xh + base) = *reinterpret_cast<uint4*>(h);
    }
}

// ---------------------------------------------------------------------------
// Kernel 2: gather + de-standardize + fp16 convert into g_Wh (needs g_table)
// ---------------------------------------------------------------------------
__global__ void __launch_bounds__(256)
gather_kernel(const int* __restrict__ idx,
              const float* __restrict__ scale, const float* __restrict__ shift)
{
    __shared__ float s_s, s_sh;
    const int o = blockIdx.x;
    if (threadIdx.x == 0) { s_s = scale[o]; s_sh = shift[o]; }
    __syncthreads();

    const int b = o * 256 + threadIdx.x;
    const int e = idx[b];
    const float s  = s_s;
    const float sh = s_sh;

    const float4* src = reinterpret_cast<const float4*>(g_table + (size_t)e * BLOCK_);
    float4 v0 = src[0], v1 = src[1], v2 = src[2], v3 = src[3];
    float blk[16] = {v0.x,v0.y,v0.z,v0.w, v1.x,v1.y,v1.z,v1.w,
                     v2.x,v2.y,v2.z,v2.w, v3.x,v3.y,v3.z,v3.w};

    __align__(16) __half h16[16];
    #pragma unroll
    for (int q = 0; q < 16; ++q) h16[q] = __float2half_rn(fmaf(blk[q], s, sh));

    const size_t base = (size_t)o * IN_F + (size_t)threadIdx.x * 16;
    reinterpret_cast<uint4*>(g_Wh + base)[0] = reinterpret_cast<uint4*>(h16)[0];
    reinterpret_cast<uint4*>(g_Wh + base)[1] = reinterpret_cast<uint4*>(h16)[1];
}

// ---------------------------------------------------------------------------
// Kernel 3: fp16 mma.sync GEMM — EXACT R5 schedule (measured 575us).
// 4 warps of 64x64, reg-double-buffered fragments, wait_group 1 at top,
// 3 stages, 2 CTAs/SM.
// ---------------------------------------------------------------------------
#define STG_BYTES 32768
#define SMEM_TOTAL (STAGES * STG_BYTES)   // 96 KB; 2 CTAs/SM

__device__ __forceinline__ void load_stage(uint32_t sbase, int buf, int it,
                                           int bm0, int bn0, int tid)
{
    const uint32_t sA = sbase + buf * STG_BYTES;
    const uint32_t sB = sA + 16384;
    const size_t k0 = (size_t)it * BK;
    #pragma unroll
    for (int i = 0; i < 8; ++i) {
        const int c = tid + i * 128;          // 0..1023
        const int row = c >> 3;
        const int cx  = c & 7;
        const uint32_t soff = SWZ((uint32_t)(row * 128 + cx * 16));
        cp16(sA + soff, g_xh + (size_t)(bm0 + row) * K_DIM + k0 + cx * 8);
        cp16(sB + soff, g_Wh + (size_t)(bn0 + row) * K_DIM + k0 + cx * 8);
    }
}

__global__ void __launch_bounds__(THREADS, 2)
gemm_kernel(const float* __restrict__ bias, float* __restrict__ C)
{
    extern __shared__ char smem[];
    const uint32_t sbase = smem_u32(smem);
    const int tid  = threadIdx.x;
    const int lane = tid & 31;
    const int w    = tid >> 5;          // 0..3
    const int wm   = w >> 1;            // m offset wm*64
    const int wn   = w & 1;             // n offset wn*64
    const int bm0  = blockIdx.y * BM;
    const int bn0  = blockIdx.x * BN;

    float acc[4][8][4];
    #pragma unroll
    for (int mt = 0; mt < 4; ++mt)
        #pragma unroll
        for (int nt = 0; nt < 8; ++nt)
            #pragma unroll
            for (int q = 0; q < 4; ++q) acc[mt][nt][q] = 0.0f;

    // Prologue: fill 2 of 3 buffers
    load_stage(sbase, 0, 0, bm0, bn0, tid);
    CP_COMMIT();
    load_stage(sbase, 1, 1, bm0, bn0, tid);
    CP_COMMIT();

    // Per-lane ldmatrix base offsets
    const int a_row = wm * 64 + (lane & 15);
    const int a_cb  = ((lane >> 4) & 1) * 16;
    const int b_row = wn * 64 + ((lane >> 4) & 1) * 8 + (lane & 7);
    const int b_cb  = ((lane >> 3) & 1) * 16;

    for (int it = 0; it < NK; ++it) {
        CP_WAIT1();
        __syncthreads();

        const int buf = it % STAGES;
        const uint32_t sA = sbase + buf * STG_BYTES;
        const uint32_t sB = sA + 16384;

        // Double-buffered fragments across kk steps
        uint32_t a[2][4][4];
        uint32_t b[2][8][2];

        // Load kk=0 fragments
        #pragma unroll
        for (int mt = 0; mt < 4; ++mt) {
            const uint32_t off = (uint32_t)((a_row + mt * 16) * 128 + a_cb);
            ldm_x4(sA + SWZ(off), a[0][mt][0], a[0][mt][1], a[0][mt][2], a[0][mt][3]);
        }
        #pragma unroll
        for (int ntp = 0; ntp < 4; ++ntp) {
            const uint32_t off = (uint32_t)((b_row + ntp * 16) * 128 + b_cb);
            uint32_t r0, r1, r2, r3;
            ldm_x4(sB + SWZ(off), r0, r1, r2, r3);
            b[0][ntp*2+0][0] = r0; b[0][ntp*2+0][1] = r1;
            b[0][ntp*2+1][0] = r2; b[0][ntp*2+1][1] = r3;
        }

        // Issue next stage's cp.async early (overlaps with MMAs below)
        const int nxt = it + 2;
        if (nxt < NK) load_stage(sbase, nxt % STAGES, nxt, bm0, bn0, tid);
        CP_COMMIT();

        #pragma unroll
        for (int kk = 0; kk < 4; ++kk) {
            const int cur = kk & 1;
            const int nxb = cur ^ 1;
            if (kk < 3) {
                const int kc = (kk + 1) * 32;
                #pragma unroll
                for (int mt = 0; mt < 4; ++mt) {
                    const uint32_t off = (uint32_t)((a_row + mt * 16) * 128 + kc + a_cb);
                    ldm_x4(sA + SWZ(off), a[nxb][mt][0], a[nxb][mt][1], a[nxb][mt][2], a[nxb][mt][3]);
                }
                #pragma unroll
                for (int ntp = 0; ntp < 4; ++ntp) {
                    const uint32_t off = (uint32_t)((b_row + ntp * 16) * 128 + kc + b_cb);
                    uint32_t r0, r1, r2, r3;
                    ldm_x4(sB + SWZ(off), r0, r1, r2, r3);
                    b[nxb][ntp*2+0][0] = r0; b[nxb][ntp*2+0][1] = r1;
                    b[nxb][ntp*2+1][0] = r2; b[nxb][ntp*2+1][1] = r3;
                }
            }
            #pragma unroll
            for (int mt = 0; mt < 4; ++mt)
                #pragma unroll
                for (int nt = 0; nt < 8; ++nt)
                    mma16816(acc[mt][nt][0], acc[mt][nt][1], acc[mt][nt][2], acc[mt][nt][3],
                             a[cur][mt][0], a[cur][mt][1], a[cur][mt][2], a[cur][mt][3],
                             b[cur][nt][0], b[cur][nt][1]);
        }
        __syncthreads();
    }

    // Epilogue
    #pragma unroll
    for (int nt = 0; nt < 8; ++nt) {
        const int col = bn0 + wn * 64 + nt * 8 + (lane & 3) * 2;
        const float bx = __ldg(bias + col);
        const float by = __ldg(bias + col + 1);
        #pragma unroll
        for (int mt = 0; mt < 4; ++mt) {
            const int r0 = bm0 + wm * 64 + mt * 16 + (lane >> 2);
            float2 v0 = make_float2(acc[mt][nt][0] + bx, acc[mt][nt][1] + by);
            float2 v1 = make_float2(acc[mt][nt][2] + bx, acc[mt][nt][3] + by);
            *reinterpret_cast<float2*>(C + (size_t)r0 * N_DIM + col) = v0;
            *reinterpret_cast<float2*>(C + (size_t)(r0 + 8) * N_DIM + col) = v1;
        }
    }
}

// ---------------------------------------------------------------------------
// kernel_launch
// ---------------------------------------------------------------------------
extern "C" void kernel_launch(void* const* d_in, const int* in_sizes, int n_in,
                              void* d_out, int out_size)
{
    const float* x        = (const float*)d_in[0];
    const int*   y_in_idx = (const int*)  d_in[1];
    const float* codebook = (const float*)d_in[2];
    const float* W1       = (const float*)d_in[3];
    const float* b1       = (const float*)d_in[4];
    const float* W2       = (const float*)d_in[5];
    const float* b2       = (const float*)d_in[6];
    const float* scale    = (const float*)d_in[7];
    const float* shift    = (const float*)d_in[8];
    const float* bias     = (const float*)d_in[9];
    float* out = (float*)d_out;

    cudaFuncSetAttribute(gemm_kernel, cudaFuncAttributeMaxDynamicSharedMemorySize, SMEM_TOTAL);

    // 1) table decode + x conversion (independent halves, overlapped in one grid)
    table_and_x_kernel<<<TBL_BLOCKS + XCONV_BLOCKS, 256>>>(codebook, W1, b1, W2, b2, x);

    // 2) W gather (depends on table)
    gather_kernel<<<OUT_F, 256>>>(y_in_idx, scale, shift);

    // 3) tensor-core GEMM (R5 schedule)
    dim3 grid(N_DIM / BN, M_ROWS / BM);
    gemm_kernel<<<grid, THREADS, SMEM_TOTAL>>>(bias, out);
}

// round 11
// speedup vs baseline: 1.5085x; 1.0283x over previous
#include <cuda_runtime.h>
#include <cuda_fp16.h>
#include <cstdint>

// ---------------------------------------------------------------------------
// Problem constants
// ---------------------------------------------------------------------------
#define IN_F   4096
#define OUT_F  4096
#define BLOCK_ 16
#define D_LAT  16
#define HID    64
#define KSIZE  65536
#define NB     (IN_F * OUT_F / BLOCK_)
#define M_ROWS 8192
#define K_DIM  4096
#define N_DIM  4096

// GEMM tiling: CTA 128x128, 4 warps of 64x64, BK=64, 3 stages (R5 config)
#define BM 128
#define BN 128
#define BK 64
#define STAGES 3
#define NK (K_DIM / BK)   // 64
#define THREADS 128

// ---------------------------------------------------------------------------
// Scratch
// ---------------------------------------------------------------------------
__device__ float  g_table[(size_t)KSIZE * BLOCK_];
__device__ __half g_Wh[(size_t)OUT_F * IN_F];
__device__ __half g_xh[(size_t)M_ROWS * IN_F];

// ---------------------------------------------------------------------------
// Helpers
// ---------------------------------------------------------------------------
__device__ __forceinline__ uint32_t smem_u32(const void* p) {
    return (uint32_t)__cvta_generic_to_shared(p);
}
#define SWZ(o) ((o) ^ (((o) >> 3) & 0x70))

__device__ __forceinline__ void cp16(uint32_t saddr, const void* gaddr) {
    asm volatile("cp.async.cg.shared.global [%0], [%1], 16;" :: "r"(saddr), "l"(gaddr));
}
#define CP_COMMIT() asm volatile("cp.async.commit_group;" ::: "memory")
#define CP_WAIT1()  asm volatile("cp.async.wait_group 1;" ::: "memory")

__device__ __forceinline__ void ldm_x4(uint32_t addr, uint32_t& r0, uint32_t& r1,
                                       uint32_t& r2, uint32_t& r3) {
    asm volatile("ldmatrix.sync.aligned.m8n8.x4.shared.b16 {%0,%1,%2,%3}, [%4];"
                 : "=r"(r0), "=r"(r1), "=r"(r2), "=r"(r3) : "r"(addr));
}

__device__ __forceinline__ void mma16816(float& c0, float& c1, float& c2, float& c3,
                                         uint32_t a0, uint32_t a1, uint32_t a2, uint32_t a3,
                                         uint32_t b0, uint32_t b1) {
    asm volatile("mma.sync.aligned.m16n8k16.row.col.f32.f16.f16.f32 "
                 "{%0,%1,%2,%3}, {%4,%5,%6,%7}, {%8,%9}, {%0,%1,%2,%3};"
                 : "+f"(c0), "+f"(c1), "+f"(c2), "+f"(c3)
                 : "r"(a0), "r"(a1), "r"(a2), "r"(a3), "r"(b0), "r"(b1));
}

// ---------------------------------------------------------------------------
// Kernel 1 (fused): table decode (LOW-REGISTER chunked MLP) + x -> fp16.
//   blocks [0, TBL_BLOCKS): decode codebook entries
//   blocks [TBL_BLOCKS, +XCONV_BLOCKS): convert x
// __launch_bounds__(256,3) caps regs (~85) so the streaming branch keeps
// >=3 CTAs/SM in flight (R10's 122-reg fusion strangled it at occ 18%).
// ---------------------------------------------------------------------------
#define TBL_BLOCKS   (KSIZE / 256)                    // 256
#define XCONV_BLOCKS ((M_ROWS * K_DIM) / (256 * 8))   // 16384

__global__ void __launch_bounds__(256, 3)
table_and_x_kernel(const float* __restrict__ codebook,
                   const float* __restrict__ W1, const float* __restrict__ b1,
                   const float* __restrict__ W2, const float* __restrict__ b2,
                   const float* __restrict__ x)
{
    if (blockIdx.x < TBL_BLOCKS) {
        __shared__ float sW1[D_LAT * HID];
        __shared__ float sW2[HID * BLOCK_];
        __shared__ float sb1[HID];
        __shared__ float sb2[BLOCK_];

        const int tid = threadIdx.x;
        for (int i = tid; i < D_LAT * HID; i += 256) sW1[i] = W1[i];
        for (int i = tid; i < HID * BLOCK_; i += 256) sW2[i] = W2[i];
        if (tid < HID)    sb1[tid] = b1[tid];
        if (tid < BLOCK_) sb2[tid] = b2[tid];
        __syncthreads();

        const int e = blockIdx.x * 256 + tid;

        float c[D_LAT];
        const float4* cb = reinterpret_cast<const float4*>(codebook + (size_t)e * D_LAT);
        {
            float4 v0 = cb[0], v1 = cb[1], v2 = cb[2], v3 = cb[3];
            c[0]=v0.x; c[1]=v0.y; c[2]=v0.z; c[3]=v0.w;
            c[4]=v1.x; c[5]=v1.y; c[6]=v1.z; c[7]=v1.w;
            c[8]=v2.x; c[9]=v2.y; c[10]=v2.z; c[11]=v2.w;
            c[12]=v3.x; c[13]=v3.y; c[14]=v3.z; c[15]=v3.w;
        }

        float blk[BLOCK_];
        #pragma unroll
        for (int k = 0; k < BLOCK_; ++k) blk[k] = sb2[k];

        // Hidden layer processed in 4 chunks of 16 to cap live registers.
        #pragma unroll
        for (int ch = 0; ch < 4; ++ch) {
            const int j0 = ch * 16;
            float h16[16];
            #pragma unroll
            for (int j = 0; j < 16; ++j) h16[j] = sb1[j0 + j];
            #pragma unroll
            for (int d = 0; d < D_LAT; ++d) {
                const float cd = c[d];
                #pragma unroll
                for (int j = 0; j < 16; ++j)
                    h16[j] = fmaf(cd, sW1[d * HID + j0 + j], h16[j]);
            }
            #pragma unroll
            for (int j = 0; j < 16; ++j) h16[j] = fmaxf(h16[j], 0.0f);
            #pragma unroll
            for (int j = 0; j < 16; ++j) {
                const float hj = h16[j];
                #pragma unroll
                for (int k = 0; k < BLOCK_; ++k)
                    blk[k] = fmaf(hj, sW2[(j0 + j) * BLOCK_ + k], blk[k]);
            }
        }

        float4* dst = reinterpret_cast<float4*>(g_table + (size_t)e * BLOCK_);
        dst[0] = make_float4(blk[0], blk[1], blk[2], blk[3]);
        dst[1] = make_float4(blk[4], blk[5], blk[6], blk[7]);
        dst[2] = make_float4(blk[8], blk[9], blk[10], blk[11]);
        dst[3] = make_float4(blk[12], blk[13], blk[14], blk[15]);
    } else {
        const size_t t = (size_t)(blockIdx.x - TBL_BLOCKS) * 256 + threadIdx.x;
        const size_t base = t * 8;
        float4 a = *reinterpret_cast<const float4*>(x + base);
        float4 b = *reinterpret_cast<const float4*>(x + base + 4);
        __align__(16) __half h[8];
        h[0]=__float2half_rn(a.x); h[1]=__float2half_rn(a.y);
        h[2]=__float2half_rn(a.z); h[3]=__float2half_rn(a.w);
        h[4]=__float2half_rn(b.x); h[5]=__float2half_rn(b.y);
        h[6]=__float2half_rn(b.z); h[7]=__float2half_rn(b.w);
        *reinterpret_cast<uint4*>(g_xh + base) = *reinterpret_cast<uint4*>(h);
    }
}

// ---------------------------------------------------------------------------
// Kernel 2: gather + de-standardize + fp16 convert into g_Wh (needs g_table)
// ---------------------------------------------------------------------------
__global__ void __launch_bounds__(256)
gather_kernel(const int* __restrict__ idx,
              const float* __restrict__ scale, const float* __restrict__ shift)
{
    __shared__ float s_s, s_sh;
    const int o = blockIdx.x;
    if (threadIdx.x == 0) { s_s = scale[o]; s_sh = shift[o]; }
    __syncthreads();

    const int b = o * 256 + threadIdx.x;
    const int e = idx[b];
    const float s  = s_s;
    const float sh = s_sh;

    const float4* src = reinterpret_cast<const float4*>(g_table + (size_t)e * BLOCK_);
    float4 v0 = src[0], v1 = src[1], v2 = src[2], v3 = src[3];
    float blk[16] = {v0.x,v0.y,v0.z,v0.w, v1.x,v1.y,v1.z,v1.w,
                     v2.x,v2.y,v2.z,v2.w, v3.x,v3.y,v3.z,v3.w};

    __align__(16) __half h16[16];
    #pragma unroll
    for (int q = 0; q < 16; ++q) h16[q] = __float2half_rn(fmaf(blk[q], s, sh));

    const size_t base = (size_t)o * IN_F + (size_t)threadIdx.x * 16;
    reinterpret_cast<uint4*>(g_Wh + base)[0] = reinterpret_cast<uint4*>(h16)[0];
    reinterpret_cast<uint4*>(g_Wh + base)[1] = reinterpret_cast<uint4*>(h16)[1];
}

// ---------------------------------------------------------------------------
// Kernel 3: fp16 mma.sync GEMM — EXACT R5 schedule (measured 575us).
// ---------------------------------------------------------------------------
#define STG_BYTES 32768
#define SMEM_TOTAL (STAGES * STG_BYTES)   // 96 KB; 2 CTAs/SM

__device__ __forceinline__ void load_stage(uint32_t sbase, int buf, int it,
                                           int bm0, int bn0, int tid)
{
    const uint32_t sA = sbase + buf * STG_BYTES;
    const uint32_t sB = sA + 16384;
    const size_t k0 = (size_t)it * BK;
    #pragma unroll
    for (int i = 0; i < 8; ++i) {
        const int c = tid + i * 128;          // 0..1023
        const int row = c >> 3;
        const int cx  = c & 7;
        const uint32_t soff = SWZ((uint32_t)(row * 128 + cx * 16));
        cp16(sA + soff, g_xh + (size_t)(bm0 + row) * K_DIM + k0 + cx * 8);
        cp16(sB + soff, g_Wh + (size_t)(bn0 + row) * K_DIM + k0 + cx * 8);
    }
}

__global__ void __launch_bounds__(THREADS, 2)
gemm_kernel(const float* __restrict__ bias, float* __restrict__ C)
{
    extern __shared__ char smem[];
    const uint32_t sbase = smem_u32(smem);
    const int tid  = threadIdx.x;
    const int lane = tid & 31;
    const int w    = tid >> 5;          // 0..3
    const int wm   = w >> 1;            // m offset wm*64
    const int wn   = w & 1;             // n offset wn*64
    const int bm0  = blockIdx.y * BM;
    const int bn0  = blockIdx.x * BN;

    float acc[4][8][4];
    #pragma unroll
    for (int mt = 0; mt < 4; ++mt)
        #pragma unroll
        for (int nt = 0; nt < 8; ++nt)
            #pragma unroll
            for (int q = 0; q < 4; ++q) acc[mt][nt][q] = 0.0f;

    // Prologue: fill 2 of 3 buffers
    load_stage(sbase, 0, 0, bm0, bn0, tid);
    CP_COMMIT();
    load_stage(sbase, 1, 1, bm0, bn0, tid);
    CP_COMMIT();

    // Per-lane ldmatrix base offsets
    const int a_row = wm * 64 + (lane & 15);
    const int a_cb  = ((lane >> 4) & 1) * 16;
    const int b_row = wn * 64 + ((lane >> 4) & 1) * 8 + (lane & 7);
    const int b_cb  = ((lane >> 3) & 1) * 16;

    for (int it = 0; it < NK; ++it) {
        CP_WAIT1();
        __syncthreads();

        const int buf = it % STAGES;
        const uint32_t sA = sbase + buf * STG_BYTES;
        const uint32_t sB = sA + 16384;

        // Double-buffered fragments across kk steps
        uint32_t a[2][4][4];
        uint32_t b[2][8][2];

        // Load kk=0 fragments
        #pragma unroll
        for (int mt = 0; mt < 4; ++mt) {
            const uint32_t off = (uint32_t)((a_row + mt * 16) * 128 + a_cb);
            ldm_x4(sA + SWZ(off), a[0][mt][0], a[0][mt][1], a[0][mt][2], a[0][mt][3]);
        }
        #pragma unroll
        for (int ntp = 0; ntp < 4; ++ntp) {
            const uint32_t off = (uint32_t)((b_row + ntp * 16) * 128 + b_cb);
            uint32_t r0, r1, r2, r3;
            ldm_x4(sB + SWZ(off), r0, r1, r2, r3);
            b[0][ntp*2+0][0] = r0; b[0][ntp*2+0][1] = r1;
            b[0][ntp*2+1][0] = r2; b[0][ntp*2+1][1] = r3;
        }

        // Issue next stage's cp.async early (overlaps with MMAs below)
        const int nxt = it + 2;
        if (nxt < NK) load_stage(sbase, nxt % STAGES, nxt, bm0, bn0, tid);
        CP_COMMIT();

        #pragma unroll
        for (int kk = 0; kk < 4; ++kk) {
            const int cur = kk & 1;
            const int nxb = cur ^ 1;
            if (kk < 3) {
                const int kc = (kk + 1) * 32;
                #pragma unroll
                for (int mt = 0; mt < 4; ++mt) {
                    const uint32_t off = (uint32_t)((a_row + mt * 16) * 128 + kc + a_cb);
                    ldm_x4(sA + SWZ(off), a[nxb][mt][0], a[nxb][mt][1], a[nxb][mt][2], a[nxb][mt][3]);
                }
                #pragma unroll
                for (int ntp = 0; ntp < 4; ++ntp) {
                    const uint32_t off = (uint32_t)((b_row + ntp * 16) * 128 + kc + b_cb);
                    uint32_t r0, r1, r2, r3;
                    ldm_x4(sB + SWZ(off), r0, r1, r2, r3);
                    b[nxb][ntp*2+0][0] = r0; b[nxb][ntp*2+0][1] = r1;
                    b[nxb][ntp*2+1][0] = r2; b[nxb][ntp*2+1][1] = r3;
                }
            }
            #pragma unroll
            for (int mt = 0; mt < 4; ++mt)
                #pragma unroll
                for (int nt = 0; nt < 8; ++nt)
                    mma16816(acc[mt][nt][0], acc[mt][nt][1], acc[mt][nt][2], acc[mt][nt][3],
                             a[cur][mt][0], a[cur][mt][1], a[cur][mt][2], a[cur][mt][3],
                             b[cur][nt][0], b[cur][nt][1]);
        }
        __syncthreads();
    }

    // Epilogue
    #pragma unroll
    for (int nt = 0; nt < 8; ++nt) {
        const int col = bn0 + wn * 64 + nt * 8 + (lane & 3) * 2;
        const float bx = __ldg(bias + col);
        const float by = __ldg(bias + col + 1);
        #pragma unroll
        for (int mt = 0; mt < 4; ++mt) {
            const int r0 = bm0 + wm * 64 + mt * 16 + (lane >> 2);
            float2 v0 = make_float2(acc[mt][nt][0] + bx, acc[mt][nt][1] + by);
            float2 v1 = make_float2(acc[mt][nt][2] + bx, acc[mt][nt][3] + by);
            *reinterpret_cast<float2*>(C + (size_t)r0 * N_DIM + col) = v0;
            *reinterpret_cast<float2*>(C + (size_t)(r0 + 8) * N_DIM + col) = v1;
        }
    }
}

// ---------------------------------------------------------------------------
// kernel_launch
// ---------------------------------------------------------------------------
extern "C" void kernel_launch(void* const* d_in, const int* in_sizes, int n_in,
                              void* d_out, int out_size)
{
    const float* x        = (const float*)d_in[0];
    const int*   y_in_idx = (const int*)  d_in[1];
    const float* codebook = (const float*)d_in[2];
    const float* W1       = (const float*)d_in[3];
    const float* b1       = (const float*)d_in[4];
    const float* W2       = (const float*)d_in[5];
    const float* b2       = (const float*)d_in[6];
    const float* scale    = (const float*)d_in[7];
    const float* shift    = (const float*)d_in[8];
    const float* bias     = (const float*)d_in[9];
    float* out = (float*)d_out;

    cudaFuncSetAttribute(gemm_kernel, cudaFuncAttributeMaxDynamicSharedMemorySize, SMEM_TOTAL);

    // 1) table decode (low-reg) + x conversion, overlapped in one grid
    table_and_x_kernel<<<TBL_BLOCKS + XCONV_BLOCKS, 256>>>(codebook, W1, b1, W2, b2, x);

    // 2) W gather (depends on table)
    gather_kernel<<<OUT_F, 256>>>(y_in_idx, scale, shift);

    // 3) tensor-core GEMM (R5 schedule)
    dim3 grid(N_DIM / BN, M_ROWS / BM);
    gemm_kernel<<<grid, THREADS, SMEM_TOTAL>>>(bias, out);
}

// round 12
// speedup vs baseline: 1.5226x; 1.0094x over previous
#include <cuda_runtime.h>
#include <cuda_fp16.h>
#include <cstdint>

// ---------------------------------------------------------------------------
// Problem constants
// ---------------------------------------------------------------------------
#define IN_F   4096
#define OUT_F  4096
#define BLOCK_ 16
#define D_LAT  16
#define HID    64
#define KSIZE  65536
#define NB     (IN_F * OUT_F / BLOCK_)
#define M_ROWS 8192
#define K_DIM  4096
#define N_DIM  4096

// GEMM tiling: CTA 128x128, 4 warps of 64x64, BK=64, 3 stages (R5 config)
#define BM 128
#define BN 128
#define BK 64
#define STAGES 3
#define NK (K_DIM / BK)   // 64
#define THREADS 128

// ---------------------------------------------------------------------------
// Scratch
// ---------------------------------------------------------------------------
__device__ float  g_table[(size_t)KSIZE * BLOCK_];
__device__ __half g_Wh[(size_t)OUT_F * IN_F];
__device__ __half g_xh[(size_t)M_ROWS * IN_F];

// ---------------------------------------------------------------------------
// Helpers
// ---------------------------------------------------------------------------
__device__ __forceinline__ uint32_t smem_u32(const void* p) {
    return (uint32_t)__cvta_generic_to_shared(p);
}
#define SWZ(o) ((o) ^ (((o) >> 3) & 0x70))

__device__ __forceinline__ void cp16(uint32_t saddr, const void* gaddr) {
    asm volatile("cp.async.cg.shared.global [%0], [%1], 16;" :: "r"(saddr), "l"(gaddr));
}
#define CP_COMMIT() asm volatile("cp.async.commit_group;" ::: "memory")
#define CP_WAIT1()  asm volatile("cp.async.wait_group 1;" ::: "memory")

__device__ __forceinline__ void ldm_x4(uint32_t addr, uint32_t& r0, uint32_t& r1,
                                       uint32_t& r2, uint32_t& r3) {
    asm volatile("ldmatrix.sync.aligned.m8n8.x4.shared.b16 {%0,%1,%2,%3}, [%4];"
                 : "=r"(r0), "=r"(r1), "=r"(r2), "=r"(r3) : "r"(addr));
}

__device__ __forceinline__ void mma16816(float& c0, float& c1, float& c2, float& c3,
                                         uint32_t a0, uint32_t a1, uint32_t a2, uint32_t a3,
                                         uint32_t b0, uint32_t b1) {
    asm volatile("mma.sync.aligned.m16n8k16.row.col.f32.f16.f16.f32 "
                 "{%0,%1,%2,%3}, {%4,%5,%6,%7}, {%8,%9}, {%0,%1,%2,%3};"
                 : "+f"(c0), "+f"(c1), "+f"(c2), "+f"(c3)
                 : "r"(a0), "r"(a1), "r"(a2), "r"(a3), "r"(b0), "r"(b1));
}

// ---------------------------------------------------------------------------
// Kernel 1: decode every codebook entry once (65536 x 16).
// R7 config: 256 CTAs x 256 threads, scalar smem loads (best measured 17.7us).
// ---------------------------------------------------------------------------
__global__ void __launch_bounds__(256)
precompute_table(const float* __restrict__ codebook,
                 const float* __restrict__ W1, const float* __restrict__ b1,
                 const float* __restrict__ W2, const float* __restrict__ b2)
{
    __shared__ float sW1[D_LAT * HID];
    __shared__ float sW2[HID * BLOCK_];
    __shared__ float sb1[HID];
    __shared__ float sb2[BLOCK_];

    const int tid = threadIdx.x;
    for (int i = tid; i < D_LAT * HID; i += 256) sW1[i] = W1[i];
    for (int i = tid; i < HID * BLOCK_; i += 256) sW2[i] = W2[i];
    if (tid < HID)    sb1[tid] = b1[tid];
    if (tid < BLOCK_) sb2[tid] = b2[tid];
    __syncthreads();

    const int e = blockIdx.x * 256 + tid;

    float c[D_LAT];
    const float4* cb = reinterpret_cast<const float4*>(codebook + (size_t)e * D_LAT);
    {
        float4 v0 = cb[0], v1 = cb[1], v2 = cb[2], v3 = cb[3];
        c[0]=v0.x; c[1]=v0.y; c[2]=v0.z; c[3]=v0.w;
        c[4]=v1.x; c[5]=v1.y; c[6]=v1.z; c[7]=v1.w;
        c[8]=v2.x; c[9]=v2.y; c[10]=v2.z; c[11]=v2.w;
        c[12]=v3.x; c[13]=v3.y; c[14]=v3.z; c[15]=v3.w;
    }

    float h[HID];
    #pragma unroll
    for (int j = 0; j < HID; ++j) h[j] = sb1[j];
    #pragma unroll
    for (int d = 0; d < D_LAT; ++d) {
        const float cd = c[d];
        #pragma unroll
        for (int j = 0; j < HID; ++j) h[j] = fmaf(cd, sW1[d * HID + j], h[j]);
    }
    #pragma unroll
    for (int j = 0; j < HID; ++j) h[j] = fmaxf(h[j], 0.0f);

    float blk[BLOCK_];
    #pragma unroll
    for (int k = 0; k < BLOCK_; ++k) blk[k] = sb2[k];
    #pragma unroll
    for (int j = 0; j < HID; ++j) {
        const float hj = h[j];
        #pragma unroll
        for (int k = 0; k < BLOCK_; ++k) blk[k] = fmaf(hj, sW2[j * BLOCK_ + k], blk[k]);
    }

    float4* dst = reinterpret_cast<float4*>(g_table + (size_t)e * BLOCK_);
    dst[0] = make_float4(blk[0], blk[1], blk[2], blk[3]);
    dst[1] = make_float4(blk[4], blk[5], blk[6], blk[7]);
    dst[2] = make_float4(blk[8], blk[9], blk[10], blk[11]);
    dst[3] = make_float4(blk[12], blk[13], blk[14], blk[15]);
}

// ---------------------------------------------------------------------------
// Kernel 2 (fused, R8 structure): gather+destandardize W  AND  x -> fp16.
// x-conversion: 16 floats/thread (4x LDG.128 front-batched) for higher MLP.
// ---------------------------------------------------------------------------
#define XCONV_BLOCKS ((M_ROWS * K_DIM) / (256 * 16))   // 8192

__global__ void __launch_bounds__(256)
prep_kernel(const int* __restrict__ idx,
            const float* __restrict__ scale, const float* __restrict__ shift,
            const float* __restrict__ x)
{
    if (blockIdx.x < OUT_F) {
        __shared__ float s_s, s_sh;
        const int o = blockIdx.x;
        if (threadIdx.x == 0) { s_s = scale[o]; s_sh = shift[o]; }
        __syncthreads();

        const int b = o * 256 + threadIdx.x;
        const int e = idx[b];
        const float s  = s_s;
        const float sh = s_sh;

        const float4* src = reinterpret_cast<const float4*>(g_table + (size_t)e * BLOCK_);
        float4 v0 = src[0], v1 = src[1], v2 = src[2], v3 = src[3];
        float blk[16] = {v0.x,v0.y,v0.z,v0.w, v1.x,v1.y,v1.z,v1.w,
                         v2.x,v2.y,v2.z,v2.w, v3.x,v3.y,v3.z,v3.w};

        __align__(16) __half h16[16];
        #pragma unroll
        for (int q = 0; q < 16; ++q) h16[q] = __float2half_rn(fmaf(blk[q], s, sh));

        const size_t base = (size_t)o * IN_F + (size_t)threadIdx.x * 16;
        reinterpret_cast<uint4*>(g_Wh + base)[0] = reinterpret_cast<uint4*>(h16)[0];
        reinterpret_cast<uint4*>(g_Wh + base)[1] = reinterpret_cast<uint4*>(h16)[1];
    } else {
        // 16 floats per thread: 4 independent LDG.128 (MLP=4), 2 STG.128
        const size_t t = (size_t)(blockIdx.x - OUT_F) * 256 + threadIdx.x;
        const size_t base = t * 16;
        float4 a0 = *reinterpret_cast<const float4*>(x + base);
        float4 a1 = *reinterpret_cast<const float4*>(x + base + 4);
        float4 a2 = *reinterpret_cast<const float4*>(x + base + 8);
        float4 a3 = *reinterpret_cast<const float4*>(x + base + 12);
        __align__(16) __half h[16];
        h[0] =__float2half_rn(a0.x); h[1] =__float2half_rn(a0.y);
        h[2] =__float2half_rn(a0.z); h[3] =__float2half_rn(a0.w);
        h[4] =__float2half_rn(a1.x); h[5] =__float2half_rn(a1.y);
        h[6] =__float2half_rn(a1.z); h[7] =__float2half_rn(a1.w);
        h[8] =__float2half_rn(a2.x); h[9] =__float2half_rn(a2.y);
        h[10]=__float2half_rn(a2.z); h[11]=__float2half_rn(a2.w);
        h[12]=__float2half_rn(a3.x); h[13]=__float2half_rn(a3.y);
        h[14]=__float2half_rn(a3.z); h[15]=__float2half_rn(a3.w);
        reinterpret_cast<uint4*>(g_xh + base)[0] = reinterpret_cast<uint4*>(h)[0];
        reinterpret_cast<uint4*>(g_xh + base)[1] = reinterpret_cast<uint4*>(h)[1];
    }
}

// ---------------------------------------------------------------------------
// Kernel 3: fp16 mma.sync GEMM — EXACT R5 schedule (measured 575us).
// ---------------------------------------------------------------------------
#define STG_BYTES 32768
#define SMEM_TOTAL (STAGES * STG_BYTES)   // 96 KB; 2 CTAs/SM

__device__ __forceinline__ void load_stage(uint32_t sbase, int buf, int it,
                                           int bm0, int bn0, int tid)
{
    const uint32_t sA = sbase + buf * STG_BYTES;
    const uint32_t sB = sA + 16384;
    const size_t k0 = (size_t)it * BK;
    #pragma unroll
    for (int i = 0; i < 8; ++i) {
        const int c = tid + i * 128;          // 0..1023
        const int row = c >> 3;
        const int cx  = c & 7;
        const uint32_t soff = SWZ((uint32_t)(row * 128 + cx * 16));
        cp16(sA + soff, g_xh + (size_t)(bm0 + row) * K_DIM + k0 + cx * 8);
        cp16(sB + soff, g_Wh + (size_t)(bn0 + row) * K_DIM + k0 + cx * 8);
    }
}

__global__ void __launch_bounds__(THREADS, 2)
gemm_kernel(const float* __restrict__ bias, float* __restrict__ C)
{
    extern __shared__ char smem[];
    const uint32_t sbase = smem_u32(smem);
    const int tid  = threadIdx.x;
    const int lane = tid & 31;
    const int w    = tid >> 5;          // 0..3
    const int wm   = w >> 1;            // m offset wm*64
    const int wn   = w & 1;             // n offset wn*64
    const int bm0  = blockIdx.y * BM;
    const int bn0  = blockIdx.x * BN;

    float acc[4][8][4];
    #pragma unroll
    for (int mt = 0; mt < 4; ++mt)
        #pragma unroll
        for (int nt = 0; nt < 8; ++nt)
            #pragma unroll
            for (int q = 0; q < 4; ++q) acc[mt][nt][q] = 0.0f;

    // Prologue: fill 2 of 3 buffers
    load_stage(sbase, 0, 0, bm0, bn0, tid);
    CP_COMMIT();
    load_stage(sbase, 1, 1, bm0, bn0, tid);
    CP_COMMIT();

    // Per-lane ldmatrix base offsets
    const int a_row = wm * 64 + (lane & 15);
    const int a_cb  = ((lane >> 4) & 1) * 16;
    const int b_row = wn * 64 + ((lane >> 4) & 1) * 8 + (lane & 7);
    const int b_cb  = ((lane >> 3) & 1) * 16;

    for (int it = 0; it < NK; ++it) {
        CP_WAIT1();
        __syncthreads();

        const int buf = it % STAGES;
        const uint32_t sA = sbase + buf * STG_BYTES;
        const uint32_t sB = sA + 16384;

        // Double-buffered fragments across kk steps
        uint32_t a[2][4][4];
        uint32_t b[2][8][2];

        // Load kk=0 fragments
        #pragma unroll
        for (int mt = 0; mt < 4; ++mt) {
            const uint32_t off = (uint32_t)((a_row + mt * 16) * 128 + a_cb);
            ldm_x4(sA + SWZ(off), a[0][mt][0], a[0][mt][1], a[0][mt][2], a[0][mt][3]);
        }
        #pragma unroll
        for (int ntp = 0; ntp < 4; ++ntp) {
            const uint32_t off = (uint32_t)((b_row + ntp * 16) * 128 + b_cb);
            uint32_t r0, r1, r2, r3;
            ldm_x4(sB + SWZ(off), r0, r1, r2, r3);
            b[0][ntp*2+0][0] = r0; b[0][ntp*2+0][1] = r1;
            b[0][ntp*2+1][0] = r2; b[0][ntp*2+1][1] = r3;
        }

        // Issue next stage's cp.async early (overlaps with MMAs below)
        const int nxt = it + 2;
        if (nxt < NK) load_stage(sbase, nxt % STAGES, nxt, bm0, bn0, tid);
        CP_COMMIT();

        #pragma unroll
        for (int kk = 0; kk < 4; ++kk) {
            const int cur = kk & 1;
            const int nxb = cur ^ 1;
            if (kk < 3) {
                const int kc = (kk + 1) * 32;
                #pragma unroll
                for (int mt = 0; mt < 4; ++mt) {
                    const uint32_t off = (uint32_t)((a_row + mt * 16) * 128 + kc + a_cb);
                    ldm_x4(sA + SWZ(off), a[nxb][mt][0], a[nxb][mt][1], a[nxb][mt][2], a[nxb][mt][3]);
                }
                #pragma unroll
                for (int ntp = 0; ntp < 4; ++ntp) {
                    const uint32_t off = (uint32_t)((b_row + ntp * 16) * 128 + kc + b_cb);
                    uint32_t r0, r1, r2, r3;
                    ldm_x4(sB + SWZ(off), r0, r1, r2, r3);
                    b[nxb][ntp*2+0][0] = r0; b[nxb][ntp*2+0][1] = r1;
                    b[nxb][ntp*2+1][0] = r2; b[nxb][ntp*2+1][1] = r3;
                }
            }
            #pragma unroll
            for (int mt = 0; mt < 4; ++mt)
                #pragma unroll
                for (int nt = 0; nt < 8; ++nt)
                    mma16816(acc[mt][nt][0], acc[mt][nt][1], acc[mt][nt][2], acc[mt][nt][3],
                             a[cur][mt][0], a[cur][mt][1], a[cur][mt][2], a[cur][mt][3],
                             b[cur][nt][0], b[cur][nt][1]);
        }
        __syncthreads();
    }

    // Epilogue
    #pragma unroll
    for (int nt = 0; nt < 8; ++nt) {
        const int col = bn0 + wn * 64 + nt * 8 + (lane & 3) * 2;
        const float bx = __ldg(bias + col);
        const float by = __ldg(bias + col + 1);
        #pragma unroll
        for (int mt = 0; mt < 4; ++mt) {
            const int r0 = bm0 + wm * 64 + mt * 16 + (lane >> 2);
            float2 v0 = make_float2(acc[mt][nt][0] + bx, acc[mt][nt][1] + by);
            float2 v1 = make_float2(acc[mt][nt][2] + bx, acc[mt][nt][3] + by);
            *reinterpret_cast<float2*>(C + (size_t)r0 * N_DIM + col) = v0;
            *reinterpret_cast<float2*>(C + (size_t)(r0 + 8) * N_DIM + col) = v1;
        }
    }
}

// ---------------------------------------------------------------------------
// kernel_launch
// ---------------------------------------------------------------------------
extern "C" void kernel_launch(void* const* d_in, const int* in_sizes, int n_in,
                              void* d_out, int out_size)
{
    const float* x        = (const float*)d_in[0];
    const int*   y_in_idx = (const int*)  d_in[1];
    const float* codebook = (const float*)d_in[2];
    const float* W1       = (const float*)d_in[3];
    const float* b1       = (const float*)d_in[4];
    const float* W2       = (const float*)d_in[5];
    const float* b2       = (const float*)d_in[6];
    const float* scale    = (const float*)d_in[7];
    const float* shift    = (const float*)d_in[8];
    const float* bias     = (const float*)d_in[9];
    float* out = (float*)d_out;

    cudaFuncSetAttribute(gemm_kernel, cudaFuncAttributeMaxDynamicSharedMemorySize, SMEM_TOTAL);

    // 1) decode each codebook entry once (R7-best config)
    precompute_table<<<KSIZE / 256, 256>>>(codebook, W1, b1, W2, b2);

    // 2) fused: W gather + x conversion (R8 structure, higher xconv ILP)
    prep_kernel<<<OUT_F + XCONV_BLOCKS, 256>>>(y_in_idx, scale, shift, x);

    // 3) tensor-core GEMM (R5 schedule, converged)
    dim3 grid(N_DIM / BN, M_ROWS / BM);
    gemm_kernel<<<grid, THREADS, SMEM_TOTAL>>>(bias, out);
}

// round 13
// speedup vs baseline: 1.5243x; 1.0011x over previous
#include <cuda_runtime.h>
#include <cuda_fp16.h>
#include <cstdint>

// ---------------------------------------------------------------------------
// Problem constants
// ---------------------------------------------------------------------------
#define IN_F   4096
#define OUT_F  4096
#define BLOCK_ 16
#define D_LAT  16
#define HID    64
#define KSIZE  65536
#define NB     (IN_F * OUT_F / BLOCK_)
#define M_ROWS 8192
#define K_DIM  4096
#define N_DIM  4096

// GEMM tiling: CTA 128x128, 4 warps of 64x64, BK=64, 3 stages (R5 config)
#define BM 128
#define BN 128
#define BK 64
#define STAGES 3
#define NK (K_DIM / BK)   // 64
#define THREADS 128

// ---------------------------------------------------------------------------
// Scratch
// ---------------------------------------------------------------------------
__device__ float  g_table[(size_t)KSIZE * BLOCK_];
__device__ __half g_Wh[(size_t)OUT_F * IN_F];
__device__ __half g_xh[(size_t)M_ROWS * IN_F];

// ---------------------------------------------------------------------------
// Helpers
// ---------------------------------------------------------------------------
__device__ __forceinline__ uint32_t smem_u32(const void* p) {
    return (uint32_t)__cvta_generic_to_shared(p);
}
#define SWZ(o) ((o) ^ (((o) >> 3) & 0x70))

__device__ __forceinline__ void cp16(uint32_t saddr, const void* gaddr) {
    asm volatile("cp.async.cg.shared.global [%0], [%1], 16;" :: "r"(saddr), "l"(gaddr));
}
#define CP_COMMIT() asm volatile("cp.async.commit_group;" ::: "memory")
#define CP_WAIT1()  asm volatile("cp.async.wait_group 1;" ::: "memory")

__device__ __forceinline__ void ldm_x4(uint32_t addr, uint32_t& r0, uint32_t& r1,
                                       uint32_t& r2, uint32_t& r3) {
    asm volatile("ldmatrix.sync.aligned.m8n8.x4.shared.b16 {%0,%1,%2,%3}, [%4];"
                 : "=r"(r0), "=r"(r1), "=r"(r2), "=r"(r3) : "r"(addr));
}

__device__ __forceinline__ void mma16816(float& c0, float& c1, float& c2, float& c3,
                                         uint32_t a0, uint32_t a1, uint32_t a2, uint32_t a3,
                                         uint32_t b0, uint32_t b1) {
    asm volatile("mma.sync.aligned.m16n8k16.row.col.f32.f16.f16.f32 "
                 "{%0,%1,%2,%3}, {%4,%5,%6,%7}, {%8,%9}, {%0,%1,%2,%3};"
                 : "+f"(c0), "+f"(c1), "+f"(c2), "+f"(c3)
                 : "r"(a0), "r"(a1), "r"(a2), "r"(a3), "r"(b0), "r"(b1));
}

// ---------------------------------------------------------------------------
// Kernel 1: decode every codebook entry once (65536 x 16). R7-best config.
// ---------------------------------------------------------------------------
__global__ void __launch_bounds__(256)
precompute_table(const float* __restrict__ codebook,
                 const float* __restrict__ W1, const float* __restrict__ b1,
                 const float* __restrict__ W2, const float* __restrict__ b2)
{
    __shared__ float sW1[D_LAT * HID];
    __shared__ float sW2[HID * BLOCK_];
    __shared__ float sb1[HID];
    __shared__ float sb2[BLOCK_];

    const int tid = threadIdx.x;
    for (int i = tid; i < D_LAT * HID; i += 256) sW1[i] = W1[i];
    for (int i = tid; i < HID * BLOCK_; i += 256) sW2[i] = W2[i];
    if (tid < HID)    sb1[tid] = b1[tid];
    if (tid < BLOCK_) sb2[tid] = b2[tid];
    __syncthreads();

    const int e = blockIdx.x * 256 + tid;

    float c[D_LAT];
    const float4* cb = reinterpret_cast<const float4*>(codebook + (size_t)e * D_LAT);
    {
        float4 v0 = cb[0], v1 = cb[1], v2 = cb[2], v3 = cb[3];
        c[0]=v0.x; c[1]=v0.y; c[2]=v0.z; c[3]=v0.w;
        c[4]=v1.x; c[5]=v1.y; c[6]=v1.z; c[7]=v1.w;
        c[8]=v2.x; c[9]=v2.y; c[10]=v2.z; c[11]=v2.w;
        c[12]=v3.x; c[13]=v3.y; c[14]=v3.z; c[15]=v3.w;
    }

    float h[HID];
    #pragma unroll
    for (int j = 0; j < HID; ++j) h[j] = sb1[j];
    #pragma unroll
    for (int d = 0; d < D_LAT; ++d) {
        const float cd = c[d];
        #pragma unroll
        for (int j = 0; j < HID; ++j) h[j] = fmaf(cd, sW1[d * HID + j], h[j]);
    }
    #pragma unroll
    for (int j = 0; j < HID; ++j) h[j] = fmaxf(h[j], 0.0f);

    float blk[BLOCK_];
    #pragma unroll
    for (int k = 0; k < BLOCK_; ++k) blk[k] = sb2[k];
    #pragma unroll
    for (int j = 0; j < HID; ++j) {
        const float hj = h[j];
        #pragma unroll
        for (int k = 0; k < BLOCK_; ++k) blk[k] = fmaf(hj, sW2[j * BLOCK_ + k], blk[k]);
    }

    float4* dst = reinterpret_cast<float4*>(g_table + (size_t)e * BLOCK_);
    dst[0] = make_float4(blk[0], blk[1], blk[2], blk[3]);
    dst[1] = make_float4(blk[4], blk[5], blk[6], blk[7]);
    dst[2] = make_float4(blk[8], blk[9], blk[10], blk[11]);
    dst[3] = make_float4(blk[12], blk[13], blk[14], blk[15]);
}

// ---------------------------------------------------------------------------
// Kernel 2 (fused): gather+destandardize W  AND  x -> fp16.
// Gather branch: direct broadcast loads of scale/shift (no smem, no barrier).
// ---------------------------------------------------------------------------
#define XCONV_BLOCKS ((M_ROWS * K_DIM) / (256 * 16))   // 8192

__global__ void __launch_bounds__(256)
prep_kernel(const int* __restrict__ idx,
            const float* __restrict__ scale, const float* __restrict__ shift,
            const float* __restrict__ x)
{
    if (blockIdx.x < OUT_F) {
        const int o = blockIdx.x;
        const float s  = __ldg(scale + o);   // broadcast: one request/warp
        const float sh = __ldg(shift + o);

        const int b = o * 256 + threadIdx.x;
        const int e = idx[b];

        const float4* src = reinterpret_cast<const float4*>(g_table + (size_t)e * BLOCK_);
        float4 v0 = src[0], v1 = src[1], v2 = src[2], v3 = src[3];
        float blk[16] = {v0.x,v0.y,v0.z,v0.w, v1.x,v1.y,v1.z,v1.w,
                         v2.x,v2.y,v2.z,v2.w, v3.x,v3.y,v3.z,v3.w};

        __align__(16) __half h16[16];
        #pragma unroll
        for (int q = 0; q < 16; ++q) h16[q] = __float2half_rn(fmaf(blk[q], s, sh));

        const size_t base = (size_t)o * IN_F + (size_t)threadIdx.x * 16;
        reinterpret_cast<uint4*>(g_Wh + base)[0] = reinterpret_cast<uint4*>(h16)[0];
        reinterpret_cast<uint4*>(g_Wh + base)[1] = reinterpret_cast<uint4*>(h16)[1];
    } else {
        // 16 floats per thread: 4 independent LDG.128, 2 STG.128
        const size_t t = (size_t)(blockIdx.x - OUT_F) * 256 + threadIdx.x;
        const size_t base = t * 16;
        float4 a0 = *reinterpret_cast<const float4*>(x + base);
        float4 a1 = *reinterpret_cast<const float4*>(x + base + 4);
        float4 a2 = *reinterpret_cast<const float4*>(x + base + 8);
        float4 a3 = *reinterpret_cast<const float4*>(x + base + 12);
        __align__(16) __half h[16];
        h[0] =__float2half_rn(a0.x); h[1] =__float2half_rn(a0.y);
        h[2] =__float2half_rn(a0.z); h[3] =__float2half_rn(a0.w);
        h[4] =__float2half_rn(a1.x); h[5] =__float2half_rn(a1.y);
        h[6] =__float2half_rn(a1.z); h[7] =__float2half_rn(a1.w);
        h[8] =__float2half_rn(a2.x); h[9] =__float2half_rn(a2.y);
        h[10]=__float2half_rn(a2.z); h[11]=__float2half_rn(a2.w);
        h[12]=__float2half_rn(a3.x); h[13]=__float2half_rn(a3.y);
        h[14]=__float2half_rn(a3.z); h[15]=__float2half_rn(a3.w);
        reinterpret_cast<uint4*>(g_xh + base)[0] = reinterpret_cast<uint4*>(h)[0];
        reinterpret_cast<uint4*>(g_xh + base)[1] = reinterpret_cast<uint4*>(h)[1];
    }
}

// ---------------------------------------------------------------------------
// Kernel 3: fp16 mma.sync GEMM — R5 schedule with the redundant bottom
// barrier removed. Safety: iteration it's load_stage targets buffer
// (it+2)%3 == (it-1)%3, whose last reads (LDSMs of iter it-1) are proven
// complete by the TOP barrier of iter it (ldmatrix is synchronous, loads
// are issued after that barrier). One __syncthreads per iteration.
// ---------------------------------------------------------------------------
#define STG_BYTES 32768
#define SMEM_TOTAL (STAGES * STG_BYTES)   // 96 KB; 2 CTAs/SM

__device__ __forceinline__ void load_stage(uint32_t sbase, int buf, int it,
                                           int bm0, int bn0, int tid)
{
    const uint32_t sA = sbase + buf * STG_BYTES;
    const uint32_t sB = sA + 16384;
    const size_t k0 = (size_t)it * BK;
    #pragma unroll
    for (int i = 0; i < 8; ++i) {
        const int c = tid + i * 128;          // 0..1023
        const int row = c >> 3;
        const int cx  = c & 7;
        const uint32_t soff = SWZ((uint32_t)(row * 128 + cx * 16));
        cp16(sA + soff, g_xh + (size_t)(bm0 + row) * K_DIM + k0 + cx * 8);
        cp16(sB + soff, g_Wh + (size_t)(bn0 + row) * K_DIM + k0 + cx * 8);
    }
}

__global__ void __launch_bounds__(THREADS, 2)
gemm_kernel(const float* __restrict__ bias, float* __restrict__ C)
{
    extern __shared__ char smem[];
    const uint32_t sbase = smem_u32(smem);
    const int tid  = threadIdx.x;
    const int lane = tid & 31;
    const int w    = tid >> 5;          // 0..3
    const int wm   = w >> 1;            // m offset wm*64
    const int wn   = w & 1;             // n offset wn*64
    const int bm0  = blockIdx.y * BM;
    const int bn0  = blockIdx.x * BN;

    float acc[4][8][4];
    #pragma unroll
    for (int mt = 0; mt < 4; ++mt)
        #pragma unroll
        for (int nt = 0; nt < 8; ++nt)
            #pragma unroll
            for (int q = 0; q < 4; ++q) acc[mt][nt][q] = 0.0f;

    // Prologue: fill 2 of 3 buffers
    load_stage(sbase, 0, 0, bm0, bn0, tid);
    CP_COMMIT();
    load_stage(sbase, 1, 1, bm0, bn0, tid);
    CP_COMMIT();

    // Per-lane ldmatrix base offsets
    const int a_row = wm * 64 + (lane & 15);
    const int a_cb  = ((lane >> 4) & 1) * 16;
    const int b_row = wn * 64 + ((lane >> 4) & 1) * 8 + (lane & 7);
    const int b_cb  = ((lane >> 3) & 1) * 16;

    for (int it = 0; it < NK; ++it) {
        CP_WAIT1();
        __syncthreads();   // sole barrier: proves iter it-1 reads complete

        const int buf = it % STAGES;
        const uint32_t sA = sbase + buf * STG_BYTES;
        const uint32_t sB = sA + 16384;

        // Double-buffered fragments across kk steps
        uint32_t a[2][4][4];
        uint32_t b[2][8][2];

        // Load kk=0 fragments
        #pragma unroll
        for (int mt = 0; mt < 4; ++mt) {
            const uint32_t off = (uint32_t)((a_row + mt * 16) * 128 + a_cb);
            ldm_x4(sA + SWZ(off), a[0][mt][0], a[0][mt][1], a[0][mt][2], a[0][mt][3]);
        }
        #pragma unroll
        for (int ntp = 0; ntp < 4; ++ntp) {
            const uint32_t off = (uint32_t)((b_row + ntp * 16) * 128 + b_cb);
            uint32_t r0, r1, r2, r3;
            ldm_x4(sB + SWZ(off), r0, r1, r2, r3);
            b[0][ntp*2+0][0] = r0; b[0][ntp*2+0][1] = r1;
            b[0][ntp*2+1][0] = r2; b[0][ntp*2+1][1] = r3;
        }

        // Issue next stage's cp.async (after the barrier -> buffer reuse safe)
        const int nxt = it + 2;
        if (nxt < NK) load_stage(sbase, nxt % STAGES, nxt, bm0, bn0, tid);
        CP_COMMIT();

        #pragma unroll
        for (int kk = 0; kk < 4; ++kk) {
            const int cur = kk & 1;
            const int nxb = cur ^ 1;
            if (kk < 3) {
                const int kc = (kk + 1) * 32;
                #pragma unroll
                for (int mt = 0; mt < 4; ++mt) {
                    const uint32_t off = (uint32_t)((a_row + mt * 16) * 128 + kc + a_cb);
                    ldm_x4(sA + SWZ(off), a[nxb][mt][0], a[nxb][mt][1], a[nxb][mt][2], a[nxb][mt][3]);
                }
                #pragma unroll
                for (int ntp = 0; ntp < 4; ++ntp) {
                    const uint32_t off = (uint32_t)((b_row + ntp * 16) * 128 + kc + b_cb);
                    uint32_t r0, r1, r2, r3;
                    ldm_x4(sB + SWZ(off), r0, r1, r2, r3);
                    b[nxb][ntp*2+0][0] = r0; b[nxb][ntp*2+0][1] = r1;
                    b[nxb][ntp*2+1][0] = r2; b[nxb][ntp*2+1][1] = r3;
                }
            }
            #pragma unroll
            for (int mt = 0; mt < 4; ++mt)
                #pragma unroll
                for (int nt = 0; nt < 8; ++nt)
                    mma16816(acc[mt][nt][0], acc[mt][nt][1], acc[mt][nt][2], acc[mt][nt][3],
                             a[cur][mt][0], a[cur][mt][1], a[cur][mt][2], a[cur][mt][3],
                             b[cur][nt][0], b[cur][nt][1]);
        }
        // (bottom __syncthreads removed — redundant, see header comment)
    }

    // Epilogue
    #pragma unroll
    for (int nt = 0; nt < 8; ++nt) {
        const int col = bn0 + wn * 64 + nt * 8 + (lane & 3) * 2;
        const float bx = __ldg(bias + col);
        const float by = __ldg(bias + col + 1);
        #pragma unroll
        for (int mt = 0; mt < 4; ++mt) {
            const int r0 = bm0 + wm * 64 + mt * 16 + (lane >> 2);
            float2 v0 = make_float2(acc[mt][nt][0] + bx, acc[mt][nt][1] + by);
            float2 v1 = make_float2(acc[mt][nt][2] + bx, acc[mt][nt][3] + by);
            *reinterpret_cast<float2*>(C + (size_t)r0 * N_DIM + col) = v0;
            *reinterpret_cast<float2*>(C + (size_t)(r0 + 8) * N_DIM + col) = v1;
        }
    }
}

// ---------------------------------------------------------------------------
// kernel_launch
// ---------------------------------------------------------------------------
extern "C" void kernel_launch(void* const* d_in, const int* in_sizes, int n_in,
                              void* d_out, int out_size)
{
    const float* x        = (const float*)d_in[0];
    const int*   y_in_idx = (const int*)  d_in[1];
    const float* codebook = (const float*)d_in[2];
    const float* W1       = (const float*)d_in[3];
    const float* b1       = (const float*)d_in[4];
    const float* W2       = (const float*)d_in[5];
    const float* b2       = (const float*)d_in[6];
    const float* scale    = (const float*)d_in[7];
    const float* shift    = (const float*)d_in[8];
    const float* bias     = (const float*)d_in[9];
    float* out = (float*)d_out;

    cudaFuncSetAttribute(gemm_kernel, cudaFuncAttributeMaxDynamicSharedMemorySize, SMEM_TOTAL);

    // 1) decode each codebook entry once
    precompute_table<<<KSIZE / 256, 256>>>(codebook, W1, b1, W2, b2);

    // 2) fused: W gather + x conversion
    prep_kernel<<<OUT_F + XCONV_BLOCKS, 256>>>(y_in_idx, scale, shift, x);

    // 3) tensor-core GEMM (R5 schedule, single barrier per iteration)
    dim3 grid(N_DIM / BN, M_ROWS / BM);
    gemm_kernel<<<grid, THREADS, SMEM_TOTAL>>>(bias, out);
}

// round 14
// speedup vs baseline: 1.5244x; 1.0001x over previous
#include <cuda_runtime.h>
#include <cuda_fp16.h>
#include <cstdint>

// ---------------------------------------------------------------------------
// Problem constants
// ---------------------------------------------------------------------------
#define IN_F   4096
#define OUT_F  4096
#define BLOCK_ 16
#define D_LAT  16
#define HID    64
#define KSIZE  65536
#define NB     (IN_F * OUT_F / BLOCK_)
#define M_ROWS 8192
#define K_DIM  4096
#define N_DIM  4096

// GEMM tiling: CTA 128x128, 4 warps of 64x64, BK=64, 3 stages (R5 config)
#define BM 128
#define BN 128
#define BK 64
#define STAGES 3
#define NK (K_DIM / BK)   // 64
#define THREADS 128

// ---------------------------------------------------------------------------
// Scratch
// ---------------------------------------------------------------------------
__device__ float  g_table[(size_t)KSIZE * BLOCK_];
__device__ __half g_Wh[(size_t)OUT_F * IN_F];
__device__ __half g_xh[(size_t)M_ROWS * IN_F];

// ---------------------------------------------------------------------------
// Helpers
// ---------------------------------------------------------------------------
__device__ __forceinline__ uint32_t smem_u32(const void* p) {
    return (uint32_t)__cvta_generic_to_shared(p);
}
#define SWZ(o) ((o) ^ (((o) >> 3) & 0x70))

__device__ __forceinline__ void cp16(uint32_t saddr, const void* gaddr) {
    asm volatile("cp.async.cg.shared.global [%0], [%1], 16;" :: "r"(saddr), "l"(gaddr));
}
#define CP_COMMIT() asm volatile("cp.async.commit_group;" ::: "memory")
#define CP_WAIT1()  asm volatile("cp.async.wait_group 1;" ::: "memory")

__device__ __forceinline__ void ldm_x4(uint32_t addr, uint32_t& r0, uint32_t& r1,
                                       uint32_t& r2, uint32_t& r3) {
    asm volatile("ldmatrix.sync.aligned.m8n8.x4.shared.b16 {%0,%1,%2,%3}, [%4];"
                 : "=r"(r0), "=r"(r1), "=r"(r2), "=r"(r3) : "r"(addr));
}

__device__ __forceinline__ void mma16816(float& c0, float& c1, float& c2, float& c3,
                                         uint32_t a0, uint32_t a1, uint32_t a2, uint32_t a3,
                                         uint32_t b0, uint32_t b1) {
    asm volatile("mma.sync.aligned.m16n8k16.row.col.f32.f16.f16.f32 "
                 "{%0,%1,%2,%3}, {%4,%5,%6,%7}, {%8,%9}, {%0,%1,%2,%3};"
                 : "+f"(c0), "+f"(c1), "+f"(c2), "+f"(c3)
                 : "r"(a0), "r"(a1), "r"(a2), "r"(a3), "r"(b0), "r"(b1));
}

// ---------------------------------------------------------------------------
// Kernel 1: decode codebook entries, TWO entries per thread.
// Each broadcast LDS of a W1/W2 weight feeds two independent FFMA chains:
// halves LDS-per-entry and doubles ILP vs the 17.7us single-entry version.
// Hidden layer in 4 chunks of 16 to cap live registers (~110).
// 256 CTAs x 128 threads x 2 entries = 65536.
// ---------------------------------------------------------------------------
__global__ void __launch_bounds__(128)
precompute_table(const float* __restrict__ codebook,
                 const float* __restrict__ W1, const float* __restrict__ b1,
                 const float* __restrict__ W2, const float* __restrict__ b2)
{
    __shared__ float sW1[D_LAT * HID];
    __shared__ float sW2[HID * BLOCK_];
    __shared__ float sb1[HID];
    __shared__ float sb2[BLOCK_];

    const int tid = threadIdx.x;
    for (int i = tid; i < D_LAT * HID; i += 128) sW1[i] = W1[i];
    for (int i = tid; i < HID * BLOCK_; i += 128) sW2[i] = W2[i];
    if (tid < HID)    sb1[tid] = b1[tid];
    if (tid < BLOCK_) sb2[tid] = b2[tid];
    __syncthreads();

    const int e0 = blockIdx.x * 256 + tid;   // entry A
    const int e1 = e0 + 128;                 // entry B

    float c0[D_LAT], c1[D_LAT];
    {
        const float4* cbA = reinterpret_cast<const float4*>(codebook + (size_t)e0 * D_LAT);
        const float4* cbB = reinterpret_cast<const float4*>(codebook + (size_t)e1 * D_LAT);
        #pragma unroll
        for (int q = 0; q < 4; ++q) {
            float4 va = cbA[q], vb = cbB[q];
            c0[q*4+0]=va.x; c0[q*4+1]=va.y; c0[q*4+2]=va.z; c0[q*4+3]=va.w;
            c1[q*4+0]=vb.x; c1[q*4+1]=vb.y; c1[q*4+2]=vb.z; c1[q*4+3]=vb.w;
        }
    }

    float blk0[BLOCK_], blk1[BLOCK_];
    #pragma unroll
    for (int k = 0; k < BLOCK_; ++k) { blk0[k] = sb2[k]; blk1[k] = sb2[k]; }

    #pragma unroll
    for (int ch = 0; ch < 4; ++ch) {
        const int j0 = ch * 16;
        float h0[16], h1[16];
        #pragma unroll
        for (int j = 0; j < 16; ++j) { h0[j] = sb1[j0 + j]; h1[j] = h0[j]; }
        #pragma unroll
        for (int d = 0; d < D_LAT; ++d) {
            const float a = c0[d];
            const float b = c1[d];
            #pragma unroll
            for (int j = 0; j < 16; ++j) {
                const float w = sW1[d * HID + j0 + j];   // one LDS -> two FFMA
                h0[j] = fmaf(a, w, h0[j]);
                h1[j] = fmaf(b, w, h1[j]);
            }
        }
        #pragma unroll
        for (int j = 0; j < 16; ++j) {
            h0[j] = fmaxf(h0[j], 0.0f);
            h1[j] = fmaxf(h1[j], 0.0f);
        }
        #pragma unroll
        for (int j = 0; j < 16; ++j) {
            const float a = h0[j];
            const float b = h1[j];
            #pragma unroll
            for (int k = 0; k < BLOCK_; ++k) {
                const float w = sW2[(j0 + j) * BLOCK_ + k];   // one LDS -> two FFMA
                blk0[k] = fmaf(a, w, blk0[k]);
                blk1[k] = fmaf(b, w, blk1[k]);
            }
        }
    }

    float4* d0 = reinterpret_cast<float4*>(g_table + (size_t)e0 * BLOCK_);
    d0[0] = make_float4(blk0[0],  blk0[1],  blk0[2],  blk0[3]);
    d0[1] = make_float4(blk0[4],  blk0[5],  blk0[6],  blk0[7]);
    d0[2] = make_float4(blk0[8],  blk0[9],  blk0[10], blk0[11]);
    d0[3] = make_float4(blk0[12], blk0[13], blk0[14], blk0[15]);
    float4* d1 = reinterpret_cast<float4*>(g_table + (size_t)e1 * BLOCK_);
    d1[0] = make_float4(blk1[0],  blk1[1],  blk1[2],  blk1[3]);
    d1[1] = make_float4(blk1[4],  blk1[5],  blk1[6],  blk1[7]);
    d1[2] = make_float4(blk1[8],  blk1[9],  blk1[10], blk1[11]);
    d1[3] = make_float4(blk1[12], blk1[13], blk1[14], blk1[15]);
}

// ---------------------------------------------------------------------------
// Kernel 2 (fused): gather+destandardize W  AND  x -> fp16.  (R13 exact)
// ---------------------------------------------------------------------------
#define XCONV_BLOCKS ((M_ROWS * K_DIM) / (256 * 16))   // 8192

__global__ void __launch_bounds__(256)
prep_kernel(const int* __restrict__ idx,
            const float* __restrict__ scale, const float* __restrict__ shift,
            const float* __restrict__ x)
{
    if (blockIdx.x < OUT_F) {
        const int o = blockIdx.x;
        const float s  = __ldg(scale + o);
        const float sh = __ldg(shift + o);

        const int b = o * 256 + threadIdx.x;
        const int e = idx[b];

        const float4* src = reinterpret_cast<const float4*>(g_table + (size_t)e * BLOCK_);
        float4 v0 = src[0], v1 = src[1], v2 = src[2], v3 = src[3];
        float blk[16] = {v0.x,v0.y,v0.z,v0.w, v1.x,v1.y,v1.z,v1.w,
                         v2.x,v2.y,v2.z,v2.w, v3.x,v3.y,v3.z,v3.w};

        __align__(16) __half h16[16];
        #pragma unroll
        for (int q = 0; q < 16; ++q) h16[q] = __float2half_rn(fmaf(blk[q], s, sh));

        const size_t base = (size_t)o * IN_F + (size_t)threadIdx.x * 16;
        reinterpret_cast<uint4*>(g_Wh + base)[0] = reinterpret_cast<uint4*>(h16)[0];
        reinterpret_cast<uint4*>(g_Wh + base)[1] = reinterpret_cast<uint4*>(h16)[1];
    } else {
        const size_t t = (size_t)(blockIdx.x - OUT_F) * 256 + threadIdx.x;
        const size_t base = t * 16;
        float4 a0 = *reinterpret_cast<const float4*>(x + base);
        float4 a1 = *reinterpret_cast<const float4*>(x + base + 4);
        float4 a2 = *reinterpret_cast<const float4*>(x + base + 8);
        float4 a3 = *reinterpret_cast<const float4*>(x + base + 12);
        __align__(16) __half h[16];
        h[0] =__float2half_rn(a0.x); h[1] =__float2half_rn(a0.y);
        h[2] =__float2half_rn(a0.z); h[3] =__float2half_rn(a0.w);
        h[4] =__float2half_rn(a1.x); h[5] =__float2half_rn(a1.y);
        h[6] =__float2half_rn(a1.z); h[7] =__float2half_rn(a1.w);
        h[8] =__float2half_rn(a2.x); h[9] =__float2half_rn(a2.y);
        h[10]=__float2half_rn(a2.z); h[11]=__float2half_rn(a2.w);
        h[12]=__float2half_rn(a3.x); h[13]=__float2half_rn(a3.y);
        h[14]=__float2half_rn(a3.z); h[15]=__float2half_rn(a3.w);
        reinterpret_cast<uint4*>(g_xh + base)[0] = reinterpret_cast<uint4*>(h)[0];
        reinterpret_cast<uint4*>(g_xh + base)[1] = reinterpret_cast<uint4*>(h)[1];
    }
}

// ---------------------------------------------------------------------------
// Kernel 3: fp16 mma.sync GEMM — R13 exact (single barrier per iteration).
// ---------------------------------------------------------------------------
#define STG_BYTES 32768
#define SMEM_TOTAL (STAGES * STG_BYTES)   // 96 KB; 2 CTAs/SM

__device__ __forceinline__ void load_stage(uint32_t sbase, int buf, int it,
                                           int bm0, int bn0, int tid)
{
    const uint32_t sA = sbase + buf * STG_BYTES;
    const uint32_t sB = sA + 16384;
    const size_t k0 = (size_t)it * BK;
    #pragma unroll
    for (int i = 0; i < 8; ++i) {
        const int c = tid + i * 128;          // 0..1023
        const int row = c >> 3;
        const int cx  = c & 7;
        const uint32_t soff = SWZ((uint32_t)(row * 128 + cx * 16));
        cp16(sA + soff, g_xh + (size_t)(bm0 + row) * K_DIM + k0 + cx * 8);
        cp16(sB + soff, g_Wh + (size_t)(bn0 + row) * K_DIM + k0 + cx * 8);
    }
}

__global__ void __launch_bounds__(THREADS, 2)
gemm_kernel(const float* __restrict__ bias, float* __restrict__ C)
{
    extern __shared__ char smem[];
    const uint32_t sbase = smem_u32(smem);
    const int tid  = threadIdx.x;
    const int lane = tid & 31;
    const int w    = tid >> 5;          // 0..3
    const int wm   = w >> 1;            // m offset wm*64
    const int wn   = w & 1;             // n offset wn*64
    const int bm0  = blockIdx.y * BM;
    const int bn0  = blockIdx.x * BN;

    float acc[4][8][4];
    #pragma unroll
    for (int mt = 0; mt < 4; ++mt)
        #pragma unroll
        for (int nt = 0; nt < 8; ++nt)
            #pragma unroll
            for (int q = 0; q < 4; ++q) acc[mt][nt][q] = 0.0f;

    // Prologue: fill 2 of 3 buffers
    load_stage(sbase, 0, 0, bm0, bn0, tid);
    CP_COMMIT();
    load_stage(sbase, 1, 1, bm0, bn0, tid);
    CP_COMMIT();

    // Per-lane ldmatrix base offsets
    const int a_row = wm * 64 + (lane & 15);
    const int a_cb  = ((lane >> 4) & 1) * 16;
    const int b_row = wn * 64 + ((lane >> 4) & 1) * 8 + (lane & 7);
    const int b_cb  = ((lane >> 3) & 1) * 16;

    for (int it = 0; it < NK; ++it) {
        CP_WAIT1();
        __syncthreads();   // sole barrier: proves iter it-1 reads complete

        const int buf = it % STAGES;
        const uint32_t sA = sbase + buf * STG_BYTES;
        const uint32_t sB = sA + 16384;

        uint32_t a[2][4][4];
        uint32_t b[2][8][2];

        // Load kk=0 fragments
        #pragma unroll
        for (int mt = 0; mt < 4; ++mt) {
            const uint32_t off = (uint32_t)((a_row + mt * 16) * 128 + a_cb);
            ldm_x4(sA + SWZ(off), a[0][mt][0], a[0][mt][1], a[0][mt][2], a[0][mt][3]);
        }
        #pragma unroll
        for (int ntp = 0; ntp < 4; ++ntp) {
            const uint32_t off = (uint32_t)((b_row + ntp * 16) * 128 + b_cb);
            uint32_t r0, r1, r2, r3;
            ldm_x4(sB + SWZ(off), r0, r1, r2, r3);
            b[0][ntp*2+0][0] = r0; b[0][ntp*2+0][1] = r1;
            b[0][ntp*2+1][0] = r2; b[0][ntp*2+1][1] = r3;
        }

        // Issue next stage's cp.async (after the barrier -> buffer reuse safe)
        const int nxt = it + 2;
        if (nxt < NK) load_stage(sbase, nxt % STAGES, nxt, bm0, bn0, tid);
        CP_COMMIT();

        #pragma unroll
        for (int kk = 0; kk < 4; ++kk) {
            const int cur = kk & 1;
            const int nxb = cur ^ 1;
            if (kk < 3) {
                const int kc = (kk + 1) * 32;
                #pragma unroll
                for (int mt = 0; mt < 4; ++mt) {
                    const uint32_t off = (uint32_t)((a_row + mt * 16) * 128 + kc + a_cb);
                    ldm_x4(sA + SWZ(off), a[nxb][mt][0], a[nxb][mt][1], a[nxb][mt][2], a[nxb][mt][3]);
                }
                #pragma unroll
                for (int ntp = 0; ntp < 4; ++ntp) {
                    const uint32_t off = (uint32_t)((b_row + ntp * 16) * 128 + kc + b_cb);
                    uint32_t r0, r1, r2, r3;
                    ldm_x4(sB + SWZ(off), r0, r1, r2, r3);
                    b[nxb][ntp*2+0][0] = r0; b[nxb][ntp*2+0][1] = r1;
                    b[nxb][ntp*2+1][0] = r2; b[nxb][ntp*2+1][1] = r3;
                }
            }
            #pragma unroll
            for (int mt = 0; mt < 4; ++mt)
                #pragma unroll
                for (int nt = 0; nt < 8; ++nt)
                    mma16816(acc[mt][nt][0], acc[mt][nt][1], acc[mt][nt][2], acc[mt][nt][3],
                             a[cur][mt][0], a[cur][mt][1], a[cur][mt][2], a[cur][mt][3],
                             b[cur][nt][0], b[cur][nt][1]);
        }
    }

    // Epilogue
    #pragma unroll
    for (int nt = 0; nt < 8; ++nt) {
        const int col = bn0 + wn * 64 + nt * 8 + (lane & 3) * 2;
        const float bx = __ldg(bias + col);
        const float by = __ldg(bias + col + 1);
        #pragma unroll
        for (int mt = 0; mt < 4; ++mt) {
            const int r0 = bm0 + wm * 64 + mt * 16 + (lane >> 2);
            float2 v0 = make_float2(acc[mt][nt][0] + bx, acc[mt][nt][1] + by);
            float2 v1 = make_float2(acc[mt][nt][2] + bx, acc[mt][nt][3] + by);
            *reinterpret_cast<float2*>(C + (size_t)r0 * N_DIM + col) = v0;
            *reinterpret_cast<float2*>(C + (size_t)(r0 + 8) * N_DIM + col) = v1;
        }
    }
}

// ---------------------------------------------------------------------------
// kernel_launch
// ---------------------------------------------------------------------------
extern "C" void kernel_launch(void* const* d_in, const int* in_sizes, int n_in,
                              void* d_out, int out_size)
{
    const float* x        = (const float*)d_in[0];
    const int*   y_in_idx = (const int*)  d_in[1];
    const float* codebook = (const float*)d_in[2];
    const float* W1       = (const float*)d_in[3];
    const float* b1       = (const float*)d_in[4];
    const float* W2       = (const float*)d_in[5];
    const float* b2       = (const float*)d_in[6];
    const float* scale    = (const float*)d_in[7];
    const float* shift    = (const float*)d_in[8];
    const float* bias     = (const float*)d_in[9];
    float* out = (float*)d_out;

    cudaFuncSetAttribute(gemm_kernel, cudaFuncAttributeMaxDynamicSharedMemorySize, SMEM_TOTAL);

    // 1) decode each codebook entry once (2 entries/thread, shared-LDS reuse)
    precompute_table<<<KSIZE / 256, 128>>>(codebook, W1, b1, W2, b2);

    // 2) fused: W gather + x conversion
    prep_kernel<<<OUT_F + XCONV_BLOCKS, 256>>>(y_in_idx, scale, shift, x);

    // 3) tensor-core GEMM (converged R5 schedule, single barrier/iter)
    dim3 grid(N_DIM / BN, M_ROWS / BM);
    gemm_kernel<<<grid, THREADS, SMEM_TOTAL>>>(bias, out);
}

// round 15
// speedup vs baseline: 1.5290x; 1.0030x over previous
#include <cuda_runtime.h>
#include <cuda_fp16.h>
#include <cstdint>

// ---------------------------------------------------------------------------
// Problem constants
// ---------------------------------------------------------------------------
#define IN_F   4096
#define OUT_F  4096
#define BLOCK_ 16
#define D_LAT  16
#define HID    64
#define KSIZE  65536
#define NB     (IN_F * OUT_F / BLOCK_)
#define M_ROWS 8192
#define K_DIM  4096
#define N_DIM  4096

// GEMM tiling: CTA 128x128, 4 warps of 64x64, BK=64, 3 stages (R5 config)
#define BM 128
#define BN 128
#define BK 64
#define STAGES 3
#define NK (K_DIM / BK)   // 64
#define THREADS 128

// ---------------------------------------------------------------------------
// Scratch
// ---------------------------------------------------------------------------
__device__ float  g_table[(size_t)KSIZE * BLOCK_];
__device__ __half g_Wh[(size_t)OUT_F * IN_F];
__device__ __half g_xh[(size_t)M_ROWS * IN_F];

// ---------------------------------------------------------------------------
// Helpers
// ---------------------------------------------------------------------------
__device__ __forceinline__ uint32_t smem_u32(const void* p) {
    return (uint32_t)__cvta_generic_to_shared(p);
}
#define SWZ(o) ((o) ^ (((o) >> 3) & 0x70))

__device__ __forceinline__ void cp16(uint32_t saddr, const void* gaddr) {
    asm volatile("cp.async.cg.shared.global [%0], [%1], 16;" :: "r"(saddr), "l"(gaddr));
}
#define CP_COMMIT() asm volatile("cp.async.commit_group;" ::: "memory")
#define CP_WAIT1()  asm volatile("cp.async.wait_group 1;" ::: "memory")

__device__ __forceinline__ void ldm_x4(uint32_t addr, uint32_t& r0, uint32_t& r1,
                                       uint32_t& r2, uint32_t& r3) {
    asm volatile("ldmatrix.sync.aligned.m8n8.x4.shared.b16 {%0,%1,%2,%3}, [%4];"
                 : "=r"(r0), "=r"(r1), "=r"(r2), "=r"(r3) : "r"(addr));
}

__device__ __forceinline__ void mma16816(float& c0, float& c1, float& c2, float& c3,
                                         uint32_t a0, uint32_t a1, uint32_t a2, uint32_t a3,
                                         uint32_t b0, uint32_t b1) {
    asm volatile("mma.sync.aligned.m16n8k16.row.col.f32.f16.f16.f32 "
                 "{%0,%1,%2,%3}, {%4,%5,%6,%7}, {%8,%9}, {%0,%1,%2,%3};"
                 : "+f"(c0), "+f"(c1), "+f"(c2), "+f"(c3)
                 : "r"(a0), "r"(a1), "r"(a2), "r"(a3), "r"(b0), "r"(b1));
}

// Grid-dependency wait (PDL). No-op if kernel wasn't launched as dependent.
__device__ __forceinline__ void grid_dep_sync() {
#if __CUDA_ARCH__ >= 900
    cudaGridDependencySynchronize();
#endif
}

// ---------------------------------------------------------------------------
// Kernel 1: decode every codebook entry once (65536 x 16). R7-best config
// (256 CTAs x 256 threads, scalar smem loads; measured 17.7us).
// ---------------------------------------------------------------------------
__global__ void __launch_bounds__(256)
precompute_table(const float* __restrict__ codebook,
                 const float* __restrict__ W1, const float* __restrict__ b1,
                 const float* __restrict__ W2, const float* __restrict__ b2)
{
    __shared__ float sW1[D_LAT * HID];
    __shared__ float sW2[HID * BLOCK_];
    __shared__ float sb1[HID];
    __shared__ float sb2[BLOCK_];

    const int tid = threadIdx.x;
    for (int i = tid; i < D_LAT * HID; i += 256) sW1[i] = W1[i];
    for (int i = tid; i < HID * BLOCK_; i += 256) sW2[i] = W2[i];
    if (tid < HID)    sb1[tid] = b1[tid];
    if (tid < BLOCK_) sb2[tid] = b2[tid];
    __syncthreads();

    const int e = blockIdx.x * 256 + tid;

    float c[D_LAT];
    const float4* cb = reinterpret_cast<const float4*>(codebook + (size_t)e * D_LAT);
    {
        float4 v0 = cb[0], v1 = cb[1], v2 = cb[2], v3 = cb[3];
        c[0]=v0.x; c[1]=v0.y; c[2]=v0.z; c[3]=v0.w;
        c[4]=v1.x; c[5]=v1.y; c[6]=v1.z; c[7]=v1.w;
        c[8]=v2.x; c[9]=v2.y; c[10]=v2.z; c[11]=v2.w;
        c[12]=v3.x; c[13]=v3.y; c[14]=v3.z; c[15]=v3.w;
    }

    float h[HID];
    #pragma unroll
    for (int j = 0; j < HID; ++j) h[j] = sb1[j];
    #pragma unroll
    for (int d = 0; d < D_LAT; ++d) {
        const float cd = c[d];
        #pragma unroll
        for (int j = 0; j < HID; ++j) h[j] = fmaf(cd, sW1[d * HID + j], h[j]);
    }
    #pragma unroll
    for (int j = 0; j < HID; ++j) h[j] = fmaxf(h[j], 0.0f);

    float blk[BLOCK_];
    #pragma unroll
    for (int k = 0; k < BLOCK_; ++k) blk[k] = sb2[k];
    #pragma unroll
    for (int j = 0; j < HID; ++j) {
        const float hj = h[j];
        #pragma unroll
        for (int k = 0; k < BLOCK_; ++k) blk[k] = fmaf(hj, sW2[j * BLOCK_ + k], blk[k]);
    }

    float4* dst = reinterpret_cast<float4*>(g_table + (size_t)e * BLOCK_);
    dst[0] = make_float4(blk[0], blk[1], blk[2], blk[3]);
    dst[1] = make_float4(blk[4], blk[5], blk[6], blk[7]);
    dst[2] = make_float4(blk[8], blk[9], blk[10], blk[11]);
    dst[3] = make_float4(blk[12], blk[13], blk[14], blk[15]);
}

// ---------------------------------------------------------------------------
// Kernel 2 (fused, PDL-overlapped with kernel 1):
//   blocks [0, XCONV_BLOCKS): x -> fp16   (independent of table; run FIRST
//     so they overlap the still-running precompute_table under PDL)
//   blocks [XCONV_BLOCKS, +OUT_F): W gather (waits on grid dependency)
// ---------------------------------------------------------------------------
#define XCONV_BLOCKS ((M_ROWS * K_DIM) / (256 * 16))   // 8192

__global__ void __launch_bounds__(256)
prep_kernel(const int* __restrict__ idx,
            const float* __restrict__ scale, const float* __restrict__ shift,
            const float* __restrict__ x)
{
    if (blockIdx.x < XCONV_BLOCKS) {
        // Independent of g_table: no dependency wait needed.
        const size_t t = (size_t)blockIdx.x * 256 + threadIdx.x;
        const size_t base = t * 16;
        float4 a0 = *reinterpret_cast<const float4*>(x + base);
        float4 a1 = *reinterpret_cast<const float4*>(x + base + 4);
        float4 a2 = *reinterpret_cast<const float4*>(x + base + 8);
        float4 a3 = *reinterpret_cast<const float4*>(x + base + 12);
        __align__(16) __half h[16];
        h[0] =__float2half_rn(a0.x); h[1] =__float2half_rn(a0.y);
        h[2] =__float2half_rn(a0.z); h[3] =__float2half_rn(a0.w);
        h[4] =__float2half_rn(a1.x); h[5] =__float2half_rn(a1.y);
        h[6] =__float2half_rn(a1.z); h[7] =__float2half_rn(a1.w);
        h[8] =__float2half_rn(a2.x); h[9] =__float2half_rn(a2.y);
        h[10]=__float2half_rn(a2.z); h[11]=__float2half_rn(a2.w);
        h[12]=__float2half_rn(a3.x); h[13]=__float2half_rn(a3.y);
        h[14]=__float2half_rn(a3.z); h[15]=__float2half_rn(a3.w);
        reinterpret_cast<uint4*>(g_xh + base)[0] = reinterpret_cast<uint4*>(h)[0];
        reinterpret_cast<uint4*>(g_xh + base)[1] = reinterpret_cast<uint4*>(h)[1];
    } else {
        // Reads g_table: must wait for precompute_table to complete.
        grid_dep_sync();

        const int o = blockIdx.x - XCONV_BLOCKS;
        const float s  = __ldg(scale + o);
        const float sh = __ldg(shift + o);

        const int b = o * 256 + threadIdx.x;
        const int e = idx[b];

        const float4* src = reinterpret_cast<const float4*>(g_table + (size_t)e * BLOCK_);
        float4 v0 = src[0], v1 = src[1], v2 = src[2], v3 = src[3];
        float blk[16] = {v0.x,v0.y,v0.z,v0.w, v1.x,v1.y,v1.z,v1.w,
                         v2.x,v2.y,v2.z,v2.w, v3.x,v3.y,v3.z,v3.w};

        __align__(16) __half h16[16];
        #pragma unroll
        for (int q = 0; q < 16; ++q) h16[q] = __float2half_rn(fmaf(blk[q], s, sh));

        const size_t base = (size_t)o * IN_F + (size_t)threadIdx.x * 16;
        reinterpret_cast<uint4*>(g_Wh + base)[0] = reinterpret_cast<uint4*>(h16)[0];
        reinterpret_cast<uint4*>(g_Wh + base)[1] = reinterpret_cast<uint4*>(h16)[1];
    }
}

// ---------------------------------------------------------------------------
// Kernel 3: fp16 mma.sync GEMM — R13 exact body + PDL entry sync.
// ---------------------------------------------------------------------------
#define STG_BYTES 32768
#define SMEM_TOTAL (STAGES * STG_BYTES)   // 96 KB; 2 CTAs/SM

__device__ __forceinline__ void load_stage(uint32_t sbase, int buf, int it,
                                           int bm0, int bn0, int tid)
{
    const uint32_t sA = sbase + buf * STG_BYTES;
    const uint32_t sB = sA + 16384;
    const size_t k0 = (size_t)it * BK;
    #pragma unroll
    for (int i = 0; i < 8; ++i) {
        const int c = tid + i * 128;          // 0..1023
        const int row = c >> 3;
        const int cx  = c & 7;
        const uint32_t soff = SWZ((uint32_t)(row * 128 + cx * 16));
        cp16(sA + soff, g_xh + (size_t)(bm0 + row) * K_DIM + k0 + cx * 8);
        cp16(sB + soff, g_Wh + (size_t)(bn0 + row) * K_DIM + k0 + cx * 8);
    }
}

__global__ void __launch_bounds__(THREADS, 2)
gemm_kernel(const float* __restrict__ bias, float* __restrict__ C)
{
    grid_dep_sync();   // PDL: wait for prep before touching g_xh/g_Wh

    extern __shared__ char smem[];
    const uint32_t sbase = smem_u32(smem);
    const int tid  = threadIdx.x;
    const int lane = tid & 31;
    const int w    = tid >> 5;          // 0..3
    const int wm   = w >> 1;            // m offset wm*64
    const int wn   = w & 1;             // n offset wn*64
    const int bm0  = blockIdx.y * BM;
    const int bn0  = blockIdx.x * BN;

    float acc[4][8][4];
    #pragma unroll
    for (int mt = 0; mt < 4; ++mt)
        #pragma unroll
        for (int nt = 0; nt < 8; ++nt)
            #pragma unroll
            for (int q = 0; q < 4; ++q) acc[mt][nt][q] = 0.0f;

    // Prologue: fill 2 of 3 buffers
    load_stage(sbase, 0, 0, bm0, bn0, tid);
    CP_COMMIT();
    load_stage(sbase, 1, 1, bm0, bn0, tid);
    CP_COMMIT();

    // Per-lane ldmatrix base offsets
    const int a_row = wm * 64 + (lane & 15);
    const int a_cb  = ((lane >> 4) & 1) * 16;
    const int b_row = wn * 64 + ((lane >> 4) & 1) * 8 + (lane & 7);
    const int b_cb  = ((lane >> 3) & 1) * 16;

    for (int it = 0; it < NK; ++it) {
        CP_WAIT1();
        __syncthreads();   // sole barrier: proves iter it-1 reads complete

        const int buf = it % STAGES;
        const uint32_t sA = sbase + buf * STG_BYTES;
        const uint32_t sB = sA + 16384;

        uint32_t a[2][4][4];
        uint32_t b[2][8][2];

        // Load kk=0 fragments
        #pragma unroll
        for (int mt = 0; mt < 4; ++mt) {
            const uint32_t off = (uint32_t)((a_row + mt * 16) * 128 + a_cb);
            ldm_x4(sA + SWZ(off), a[0][mt][0], a[0][mt][1], a[0][mt][2], a[0][mt][3]);
        }
        #pragma unroll
        for (int ntp = 0; ntp < 4; ++ntp) {
            const uint32_t off = (uint32_t)((b_row + ntp * 16) * 128 + b_cb);
            uint32_t r0, r1, r2, r3;
            ldm_x4(sB + SWZ(off), r0, r1, r2, r3);
            b[0][ntp*2+0][0] = r0; b[0][ntp*2+0][1] = r1;
            b[0][ntp*2+1][0] = r2; b[0][ntp*2+1][1] = r3;
        }

        // Issue next stage's cp.async (after the barrier -> buffer reuse safe)
        const int nxt = it + 2;
        if (nxt < NK) load_stage(sbase, nxt % STAGES, nxt, bm0, bn0, tid);
        CP_COMMIT();

        #pragma unroll
        for (int kk = 0; kk < 4; ++kk) {
            const int cur = kk & 1;
            const int nxb = cur ^ 1;
            if (kk < 3) {
                const int kc = (kk + 1) * 32;
                #pragma unroll
                for (int mt = 0; mt < 4; ++mt) {
                    const uint32_t off = (uint32_t)((a_row + mt * 16) * 128 + kc + a_cb);
                    ldm_x4(sA + SWZ(off), a[nxb][mt][0], a[nxb][mt][1], a[nxb][mt][2], a[nxb][mt][3]);
                }
                #pragma unroll
                for (int ntp = 0; ntp < 4; ++ntp) {
                    const uint32_t off = (uint32_t)((b_row + ntp * 16) * 128 + kc + b_cb);
                    uint32_t r0, r1, r2, r3;
                    ldm_x4(sB + SWZ(off), r0, r1, r2, r3);
                    b[nxb][ntp*2+0][0] = r0; b[nxb][ntp*2+0][1] = r1;
                    b[nxb][ntp*2+1][0] = r2; b[nxb][ntp*2+1][1] = r3;
                }
            }
            #pragma unroll
            for (int mt = 0; mt < 4; ++mt)
                #pragma unroll
                for (int nt = 0; nt < 8; ++nt)
                    mma16816(acc[mt][nt][0], acc[mt][nt][1], acc[mt][nt][2], acc[mt][nt][3],
                             a[cur][mt][0], a[cur][mt][1], a[cur][mt][2], a[cur][mt][3],
                             b[cur][nt][0], b[cur][nt][1]);
        }
    }

    // Epilogue
    #pragma unroll
    for (int nt = 0; nt < 8; ++nt) {
        const int col = bn0 + wn * 64 + nt * 8 + (lane & 3) * 2;
        const float bx = __ldg(bias + col);
        const float by = __ldg(bias + col + 1);
        #pragma unroll
        for (int mt = 0; mt < 4; ++mt) {
            const int r0 = bm0 + wm * 64 + mt * 16 + (lane >> 2);
            float2 v0 = make_float2(acc[mt][nt][0] + bx, acc[mt][nt][1] + by);
            float2 v1 = make_float2(acc[mt][nt][2] + bx, acc[mt][nt][3] + by);
            *reinterpret_cast<float2*>(C + (size_t)r0 * N_DIM + col) = v0;
            *reinterpret_cast<float2*>(C + (size_t)(r0 + 8) * N_DIM + col) = v1;
        }
    }
}

// ---------------------------------------------------------------------------
// kernel_launch — PDL overlap: prep launches while table still runs (xconv
// blocks proceed immediately; gather blocks grid-dep-sync). Same for GEMM.
// ---------------------------------------------------------------------------
extern "C" void kernel_launch(void* const* d_in, const int* in_sizes, int n_in,
                              void* d_out, int out_size)
{
    const float* x        = (const float*)d_in[0];
    const int*   y_in_idx = (const int*)  d_in[1];
    const float* codebook = (const float*)d_in[2];
    const float* W1       = (const float*)d_in[3];
    const float* b1       = (const float*)d_in[4];
    const float* W2       = (const float*)d_in[5];
    const float* b2       = (const float*)d_in[6];
    const float* scale    = (const float*)d_in[7];
    const float* shift    = (const float*)d_in[8];
    const float* bias     = (const float*)d_in[9];
    float* out = (float*)d_out;

    cudaFuncSetAttribute(gemm_kernel, cudaFuncAttributeMaxDynamicSharedMemorySize, SMEM_TOTAL);

    // 1) decode each codebook entry once
    precompute_table<<<KSIZE / 256, 256>>>(codebook, W1, b1, W2, b2);

    // 2) prep (PDL: overlaps with table; gather blocks wait via grid sync)
    {
        cudaLaunchAttribute attrs[1];
        attrs[0].id = cudaLaunchAttributeProgrammaticStreamSerialization;
        attrs[0].val.programmaticStreamSerializationAllowed = 1;
        cudaLaunchConfig_t cfg = {};
        cfg.gridDim  = dim3(XCONV_BLOCKS + OUT_F, 1, 1);
        cfg.blockDim = dim3(256, 1, 1);
        cfg.attrs = attrs;
        cfg.numAttrs = 1;
        cudaLaunchKernelEx(&cfg, prep_kernel, y_in_idx, scale, shift, x);
    }

    // 3) GEMM (PDL: early launch; waits at entry before loading g_xh/g_Wh)
    {
        cudaLaunchAttribute attrs[1];
        attrs[0].id = cudaLaunchAttributeProgrammaticStreamSerialization;
        attrs[0].val.programmaticStreamSerializationAllowed = 1;
        cudaLaunchConfig_t cfg = {};
        cfg.gridDim  = dim3(N_DIM / BN, M_ROWS / BM, 1);
        cfg.blockDim = dim3(THREADS, 1, 1);
        cfg.dynamicSmemBytes = SMEM_TOTAL;
        cfg.attrs = attrs;
        cfg.numAttrs = 1;
        cudaLaunchKernelEx(&cfg, gemm_kernel, bias, out);
    }
}

// round 16
// speedup vs baseline: 1.5434x; 1.0094x over previous
#include <cuda_runtime.h>
#include <cuda_fp16.h>
#include <cstdint>

// ---------------------------------------------------------------------------
// Problem constants
// ---------------------------------------------------------------------------
#define IN_F   4096
#define OUT_F  4096
#define BLOCK_ 16
#define D_LAT  16
#define HID    64
#define KSIZE  65536
#define NB     (IN_F * OUT_F / BLOCK_)
#define M_ROWS 8192
#define K_DIM  4096
#define N_DIM  4096

// GEMM tiling: CTA 128x128, 4 warps of 64x64, BK=64, 3 stages (R5 config)
#define BM 128
#define BN 128
#define BK 64
#define STAGES 3
#define NK (K_DIM / BK)   // 64
#define THREADS 128

// ---------------------------------------------------------------------------
// Scratch
// ---------------------------------------------------------------------------
__device__ float  g_table[(size_t)KSIZE * BLOCK_];
__device__ __half g_Wh[(size_t)OUT_F * IN_F];
__device__ __half g_xh[(size_t)M_ROWS * IN_F];

// ---------------------------------------------------------------------------
// Helpers
// ---------------------------------------------------------------------------
__device__ __forceinline__ uint32_t smem_u32(const void* p) {
    return (uint32_t)__cvta_generic_to_shared(p);
}
#define SWZ(o) ((o) ^ (((o) >> 3) & 0x70))

__device__ __forceinline__ void cp16(uint32_t saddr, const void* gaddr) {
    asm volatile("cp.async.cg.shared.global [%0], [%1], 16;" :: "r"(saddr), "l"(gaddr));
}
#define CP_COMMIT() asm volatile("cp.async.commit_group;" ::: "memory")
#define CP_WAIT1()  asm volatile("cp.async.wait_group 1;" ::: "memory")

__device__ __forceinline__ void ldm_x4(uint32_t addr, uint32_t& r0, uint32_t& r1,
                                       uint32_t& r2, uint32_t& r3) {
    asm volatile("ldmatrix.sync.aligned.m8n8.x4.shared.b16 {%0,%1,%2,%3}, [%4];"
                 : "=r"(r0), "=r"(r1), "=r"(r2), "=r"(r3) : "r"(addr));
}

__device__ __forceinline__ void mma16816(float& c0, float& c1, float& c2, float& c3,
                                         uint32_t a0, uint32_t a1, uint32_t a2, uint32_t a3,
                                         uint32_t b0, uint32_t b1) {
    asm volatile("mma.sync.aligned.m16n8k16.row.col.f32.f16.f16.f32 "
                 "{%0,%1,%2,%3}, {%4,%5,%6,%7}, {%8,%9}, {%0,%1,%2,%3};"
                 : "+f"(c0), "+f"(c1), "+f"(c2), "+f"(c3)
                 : "r"(a0), "r"(a1), "r"(a2), "r"(a3), "r"(b0), "r"(b1));
}

// PDL primitives. Trigger: allow dependent grid to LAUNCH now.
// Sync: wait until preceding grid COMPLETES (memory visible).
__device__ __forceinline__ void grid_dep_sync() {
#if __CUDA_ARCH__ >= 900
    cudaGridDependencySynchronize();
#endif
}
__device__ __forceinline__ void grid_trigger_launch() {
#if __CUDA_ARCH__ >= 900
    cudaTriggerProgrammaticLaunchCompletion();
#endif
}

// ---------------------------------------------------------------------------
// Kernel 1: decode every codebook entry once (65536 x 16). R7-best config.
// Triggers PDL immediately so prep's xconv blocks overlap with this kernel.
// ---------------------------------------------------------------------------
__global__ void __launch_bounds__(256)
precompute_table(const float* __restrict__ codebook,
                 const float* __restrict__ W1, const float* __restrict__ b1,
                 const float* __restrict__ W2, const float* __restrict__ b2)
{
    grid_trigger_launch();   // dependent prep grid may launch now; its gather
                             // blocks still wait for THIS grid to complete.

    __shared__ float sW1[D_LAT * HID];
    __shared__ float sW2[HID * BLOCK_];
    __shared__ float sb1[HID];
    __shared__ float sb2[BLOCK_];

    const int tid = threadIdx.x;
    for (int i = tid; i < D_LAT * HID; i += 256) sW1[i] = W1[i];
    for (int i = tid; i < HID * BLOCK_; i += 256) sW2[i] = W2[i];
    if (tid < HID)    sb1[tid] = b1[tid];
    if (tid < BLOCK_) sb2[tid] = b2[tid];
    __syncthreads();

    const int e = blockIdx.x * 256 + tid;

    float c[D_LAT];
    const float4* cb = reinterpret_cast<const float4*>(codebook + (size_t)e * D_LAT);
    {
        float4 v0 = cb[0], v1 = cb[1], v2 = cb[2], v3 = cb[3];
        c[0]=v0.x; c[1]=v0.y; c[2]=v0.z; c[3]=v0.w;
        c[4]=v1.x; c[5]=v1.y; c[6]=v1.z; c[7]=v1.w;
        c[8]=v2.x; c[9]=v2.y; c[10]=v2.z; c[11]=v2.w;
        c[12]=v3.x; c[13]=v3.y; c[14]=v3.z; c[15]=v3.w;
    }

    float h[HID];
    #pragma unroll
    for (int j = 0; j < HID; ++j) h[j] = sb1[j];
    #pragma unroll
    for (int d = 0; d < D_LAT; ++d) {
        const float cd = c[d];
        #pragma unroll
        for (int j = 0; j < HID; ++j) h[j] = fmaf(cd, sW1[d * HID + j], h[j]);
    }
    #pragma unroll
    for (int j = 0; j < HID; ++j) h[j] = fmaxf(h[j], 0.0f);

    float blk[BLOCK_];
    #pragma unroll
    for (int k = 0; k < BLOCK_; ++k) blk[k] = sb2[k];
    #pragma unroll
    for (int j = 0; j < HID; ++j) {
        const float hj = h[j];
        #pragma unroll
        for (int k = 0; k < BLOCK_; ++k) blk[k] = fmaf(hj, sW2[j * BLOCK_ + k], blk[k]);
    }

    float4* dst = reinterpret_cast<float4*>(g_table + (size_t)e * BLOCK_);
    dst[0] = make_float4(blk[0], blk[1], blk[2], blk[3]);
    dst[1] = make_float4(blk[4], blk[5], blk[6], blk[7]);
    dst[2] = make_float4(blk[8], blk[9], blk[10], blk[11]);
    dst[3] = make_float4(blk[12], blk[13], blk[14], blk[15]);
}

// ---------------------------------------------------------------------------
// Kernel 2 (fused, PDL-overlapped with kernel 1):
//   blocks [0, XCONV_BLOCKS): x -> fp16  (independent of table, no wait)
//   blocks [XCONV_BLOCKS, +OUT_F): W gather (grid_dep_sync before g_table)
// Triggers its own PDL early so the GEMM's launch gap is hidden.
// ---------------------------------------------------------------------------
#define XCONV_BLOCKS ((M_ROWS * K_DIM) / (256 * 16))   // 8192

__global__ void __launch_bounds__(256)
prep_kernel(const int* __restrict__ idx,
            const float* __restrict__ scale, const float* __restrict__ shift,
            const float* __restrict__ x)
{
    grid_trigger_launch();   // GEMM grid may launch; it grid_dep_syncs anyway.

    if (blockIdx.x < XCONV_BLOCKS) {
        const size_t t = (size_t)blockIdx.x * 256 + threadIdx.x;
        const size_t base = t * 16;
        float4 a0 = *reinterpret_cast<const float4*>(x + base);
        float4 a1 = *reinterpret_cast<const float4*>(x + base + 4);
        float4 a2 = *reinterpret_cast<const float4*>(x + base + 8);
        float4 a3 = *reinterpret_cast<const float4*>(x + base + 12);
        __align__(16) __half h[16];
        h[0] =__float2half_rn(a0.x); h[1] =__float2half_rn(a0.y);
        h[2] =__float2half_rn(a0.z); h[3] =__float2half_rn(a0.w);
        h[4] =__float2half_rn(a1.x); h[5] =__float2half_rn(a1.y);
        h[6] =__float2half_rn(a1.z); h[7] =__float2half_rn(a1.w);
        h[8] =__float2half_rn(a2.x); h[9] =__float2half_rn(a2.y);
        h[10]=__float2half_rn(a2.z); h[11]=__float2half_rn(a2.w);
        h[12]=__float2half_rn(a3.x); h[13]=__float2half_rn(a3.y);
        h[14]=__float2half_rn(a3.z); h[15]=__float2half_rn(a3.w);
        reinterpret_cast<uint4*>(g_xh + base)[0] = reinterpret_cast<uint4*>(h)[0];
        reinterpret_cast<uint4*>(g_xh + base)[1] = reinterpret_cast<uint4*>(h)[1];
    } else {
        grid_dep_sync();     // wait for precompute_table to COMPLETE

        const int o = blockIdx.x - XCONV_BLOCKS;
        const float s  = __ldg(scale + o);
        const float sh = __ldg(shift + o);

        const int b = o * 256 + threadIdx.x;
        const int e = idx[b];

        const float4* src = reinterpret_cast<const float4*>(g_table + (size_t)e * BLOCK_);
        float4 v0 = src[0], v1 = src[1], v2 = src[2], v3 = src[3];
        float blk[16] = {v0.x,v0.y,v0.z,v0.w, v1.x,v1.y,v1.z,v1.w,
                         v2.x,v2.y,v2.z,v2.w, v3.x,v3.y,v3.z,v3.w};

        __align__(16) __half h16[16];
        #pragma unroll
        for (int q = 0; q < 16; ++q) h16[q] = __float2half_rn(fmaf(blk[q], s, sh));

        const size_t base = (size_t)o * IN_F + (size_t)threadIdx.x * 16;
        reinterpret_cast<uint4*>(g_Wh + base)[0] = reinterpret_cast<uint4*>(h16)[0];
        reinterpret_cast<uint4*>(g_Wh + base)[1] = reinterpret_cast<uint4*>(h16)[1];
    }
}

// ---------------------------------------------------------------------------
// Kernel 3: fp16 mma.sync GEMM — R13 exact body + PDL entry sync.
// ---------------------------------------------------------------------------
#define STG_BYTES 32768
#define SMEM_TOTAL (STAGES * STG_BYTES)   // 96 KB; 2 CTAs/SM

__device__ __forceinline__ void load_stage(uint32_t sbase, int buf, int it,
                                           int bm0, int bn0, int tid)
{
    const uint32_t sA = sbase + buf * STG_BYTES;
    const uint32_t sB = sA + 16384;
    const size_t k0 = (size_t)it * BK;
    #pragma unroll
    for (int i = 0; i < 8; ++i) {
        const int c = tid + i * 128;          // 0..1023
        const int row = c >> 3;
        const int cx  = c & 7;
        const uint32_t soff = SWZ((uint32_t)(row * 128 + cx * 16));
        cp16(sA + soff, g_xh + (size_t)(bm0 + row) * K_DIM + k0 + cx * 8);
        cp16(sB + soff, g_Wh + (size_t)(bn0 + row) * K_DIM + k0 + cx * 8);
    }
}

__global__ void __launch_bounds__(THREADS, 2)
gemm_kernel(const float* __restrict__ bias, float* __restrict__ C)
{
    grid_dep_sync();   // PDL: wait for prep before touching g_xh/g_Wh

    extern __shared__ char smem[];
    const uint32_t sbase = smem_u32(smem);
    const int tid  = threadIdx.x;
    const int lane = tid & 31;
    const int w    = tid >> 5;          // 0..3
    const int wm   = w >> 1;            // m offset wm*64
    const int wn   = w & 1;             // n offset wn*64
    const int bm0  = blockIdx.y * BM;
    const int bn0  = blockIdx.x * BN;

    float acc[4][8][4];
    #pragma unroll
    for (int mt = 0; mt < 4; ++mt)
        #pragma unroll
        for (int nt = 0; nt < 8; ++nt)
            #pragma unroll
            for (int q = 0; q < 4; ++q) acc[mt][nt][q] = 0.0f;

    // Prologue: fill 2 of 3 buffers
    load_stage(sbase, 0, 0, bm0, bn0, tid);
    CP_COMMIT();
    load_stage(sbase, 1, 1, bm0, bn0, tid);
    CP_COMMIT();

    // Per-lane ldmatrix base offsets
    const int a_row = wm * 64 + (lane & 15);
    const int a_cb  = ((lane >> 4) & 1) * 16;
    const int b_row = wn * 64 + ((lane >> 4) & 1) * 8 + (lane & 7);
    const int b_cb  = ((lane >> 3) & 1) * 16;

    for (int it = 0; it < NK; ++it) {
        CP_WAIT1();
        __syncthreads();   // sole barrier: proves iter it-1 reads complete

        const int buf = it % STAGES;
        const uint32_t sA = sbase + buf * STG_BYTES;
        const uint32_t sB = sA + 16384;

        uint32_t a[2][4][4];
        uint32_t b[2][8][2];

        // Load kk=0 fragments
        #pragma unroll
        for (int mt = 0; mt < 4; ++mt) {
            const uint32_t off = (uint32_t)((a_row + mt * 16) * 128 + a_cb);
            ldm_x4(sA + SWZ(off), a[0][mt][0], a[0][mt][1], a[0][mt][2], a[0][mt][3]);
        }
        #pragma unroll
        for (int ntp = 0; ntp < 4; ++ntp) {
            const uint32_t off = (uint32_t)((b_row + ntp * 16) * 128 + b_cb);
            uint32_t r0, r1, r2, r3;
            ldm_x4(sB + SWZ(off), r0, r1, r2, r3);
            b[0][ntp*2+0][0] = r0; b[0][ntp*2+0][1] = r1;
            b[0][ntp*2+1][0] = r2; b[0][ntp*2+1][1] = r3;
        }

        // Issue next stage's cp.async (after the barrier -> buffer reuse safe)
        const int nxt = it + 2;
        if (nxt < NK) load_stage(sbase, nxt % STAGES, nxt, bm0, bn0, tid);
        CP_COMMIT();

        #pragma unroll
        for (int kk = 0; kk < 4; ++kk) {
            const int cur = kk & 1;
            const int nxb = cur ^ 1;
            if (kk < 3) {
                const int kc = (kk + 1) * 32;
                #pragma unroll
                for (int mt = 0; mt < 4; ++mt) {
                    const uint32_t off = (uint32_t)((a_row + mt * 16) * 128 + kc + a_cb);
                    ldm_x4(sA + SWZ(off), a[nxb][mt][0], a[nxb][mt][1], a[nxb][mt][2], a[nxb][mt][3]);
                }
                #pragma unroll
                for (int ntp = 0; ntp < 4; ++ntp) {
                    const uint32_t off = (uint32_t)((b_row + ntp * 16) * 128 + kc + b_cb);
                    uint32_t r0, r1, r2, r3;
                    ldm_x4(sB + SWZ(off), r0, r1, r2, r3);
                    b[nxb][ntp*2+0][0] = r0; b[nxb][ntp*2+0][1] = r1;
                    b[nxb][ntp*2+1][0] = r2; b[nxb][ntp*2+1][1] = r3;
                }
            }
            #pragma unroll
            for (int mt = 0; mt < 4; ++mt)
                #pragma unroll
                for (int nt = 0; nt < 8; ++nt)
                    mma16816(acc[mt][nt][0], acc[mt][nt][1], acc[mt][nt][2], acc[mt][nt][3],
                             a[cur][mt][0], a[cur][mt][1], a[cur][mt][2], a[cur][mt][3],
                             b[cur][nt][0], b[cur][nt][1]);
        }
    }

    // Epilogue
    #pragma unroll
    for (int nt = 0; nt < 8; ++nt) {
        const int col = bn0 + wn * 64 + nt * 8 + (lane & 3) * 2;
        const float bx = __ldg(bias + col);
        const float by = __ldg(bias + col + 1);
        #pragma unroll
        for (int mt = 0; mt < 4; ++mt) {
            const int r0 = bm0 + wm * 64 + mt * 16 + (lane >> 2);
            float2 v0 = make_float2(acc[mt][nt][0] + bx, acc[mt][nt][1] + by);
            float2 v1 = make_float2(acc[mt][nt][2] + bx, acc[mt][nt][3] + by);
            *reinterpret_cast<float2*>(C + (size_t)r0 * N_DIM + col) = v0;
            *reinterpret_cast<float2*>(C + (size_t)(r0 + 8) * N_DIM + col) = v1;
        }
    }
}

// ---------------------------------------------------------------------------
// kernel_launch — PDL with EARLY triggers: prep overlaps the table kernel
// (xconv blocks run immediately); GEMM launch gap hidden behind prep.
// ---------------------------------------------------------------------------
extern "C" void kernel_launch(void* const* d_in, const int* in_sizes, int n_in,
                              void* d_out, int out_size)
{
    const float* x        = (const float*)d_in[0];
    const int*   y_in_idx = (const int*)  d_in[1];
    const float* codebook = (const float*)d_in[2];
    const float* W1       = (const float*)d_in[3];
    const float* b1       = (const float*)d_in[4];
    const float* W2       = (const float*)d_in[5];
    const float* b2       = (const float*)d_in[6];
    const float* scale    = (const float*)d_in[7];
    const float* shift    = (const float*)d_in[8];
    const float* bias     = (const float*)d_in[9];
    float* out = (float*)d_out;

    cudaFuncSetAttribute(gemm_kernel, cudaFuncAttributeMaxDynamicSharedMemorySize, SMEM_TOTAL);

    // 1) decode each codebook entry once (triggers PDL at entry)
    precompute_table<<<KSIZE / 256, 256>>>(codebook, W1, b1, W2, b2);

    // 2) prep (PDL: launches while table still runs; gather blocks wait)
    {
        cudaLaunchAttribute attrs[1];
        attrs[0].id = cudaLaunchAttributeProgrammaticStreamSerialization;
        attrs[0].val.programmaticStreamSerializationAllowed = 1;
        cudaLaunchConfig_t cfg = {};
        cfg.gridDim  = dim3(XCONV_BLOCKS + OUT_F, 1, 1);
        cfg.blockDim = dim3(256, 1, 1);
        cfg.attrs = attrs;
        cfg.numAttrs = 1;
        cudaLaunchKernelEx(&cfg, prep_kernel, y_in_idx, scale, shift, x);
    }

    // 3) GEMM (PDL: early launch; waits at entry before loading g_xh/g_Wh)
    {
        cudaLaunchAttribute attrs[1];
        attrs[0].id = cudaLaunchAttributeProgrammaticStreamSerialization;
        attrs[0].val.programmaticStreamSerializationAllowed = 1;
        cudaLaunchConfig_t cfg = {};
        cfg.gridDim  = dim3(N_DIM / BN, M_ROWS / BM, 1);
        cfg.blockDim = dim3(THREADS, 1, 1);
        cfg.dynamicSmemBytes = SMEM_TOTAL;
        cfg.attrs = attrs;
        cfg.numAttrs = 1;
        cudaLaunchKernelEx(&cfg, gemm_kernel, bias, out);
    }
}